// round 1
// baseline (speedup 1.0000x reference)
#include <cuda_runtime.h>
#include <math.h>
#include <stdint.h>

// Problem constants
#define Bn   16
#define Cn   768
#define Sn   729
#define Hn   8
#define Dn   96
#define En   3
#define HIDn 3072
#define NTOK (Bn*Sn)          // 11664

// ---------------- scratch (device globals; no allocation allowed) -----------
__device__ float d_mu[Bn], d_rstd[Bn];
__device__ float d_tok[(size_t)NTOK*Cn];                 // xn, [b,s,c]
__device__ float d_q[(size_t)Bn*Hn*Sn*Dn];
__device__ float d_k[(size_t)Bn*Hn*Sn*Dn];
__device__ float d_v[(size_t)Bn*Hn*Sn*Dn];
__device__ float d_sc[(size_t)Bn*Hn*Sn*Sn];              // scores / probs, 272MB
__device__ float d_ctx[(size_t)NTOK*Cn];
__device__ float d_x2[(size_t)NTOK*Cn];                  // x + attn_out, [b,s,c]
__device__ int   d_eid[NTOK];
__device__ float d_mg[NTOK];
__device__ float d_gs[NTOK];
__device__ float d_denom[Sn*En];
__device__ int   d_cnt[En];
__device__ int   d_list[En*NTOK];
__device__ float d_hmid[(size_t)NTOK*HIDn];              // 143MB, indexed by token
__device__ float d_moe[(size_t)NTOK*Cn];

// ---------------- generic tiled fp32 GEMM core ------------------------------
// C[m,n] = sum_k A(m,k)*B(k,n); loaders are bounds-free (core guards),
// BKF=true means B loader is K-fast in memory (for B^T layouts).
template<int BM,int BN,int BK,int TM,int TN,bool BKF, class FA,class FB,class FC>
__device__ __forceinline__ void gemm_core(int M,int N,int K, FA fA, FB fB, FC fC){
    constexpr int TX = BN/TN, TY = BM/TM, NT = TX*TY;
    __shared__ float As[BK][BM+4];
    __shared__ float Bs[BK][BN+4];
    const int tid = threadIdx.x;
    const int tx  = tid % TX, ty = tid / TX;
    const int row0 = blockIdx.x * BM;
    const int col0 = blockIdx.y * BN;
    if (row0 >= M) return;

    float acc[TM][TN];
    #pragma unroll
    for (int i=0;i<TM;i++)
        #pragma unroll
        for (int j=0;j<TN;j++) acc[i][j]=0.f;

    for (int k0=0;k0<K;k0+=BK){
        #pragma unroll
        for (int l=tid; l<BM*BK; l+=NT){
            int kk = l % BK, mm = l / BK;
            int m = row0+mm, k = k0+kk;
            As[kk][mm] = (m<M && k<K) ? fA(m,k) : 0.f;
        }
        #pragma unroll
        for (int l=tid; l<BN*BK; l+=NT){
            int kk, nn;
            if (BKF){ kk = l % BK; nn = l / BK; }
            else    { nn = l % BN; kk = l / BN; }
            int k = k0+kk, n = col0+nn;
            Bs[kk][nn] = (k<K && n<N) ? fB(k,n) : 0.f;
        }
        __syncthreads();
        #pragma unroll
        for (int kk=0;kk<BK;kk++){
            float a[TM], b[TN];
            #pragma unroll
            for (int i=0;i<TM;i++) a[i]=As[kk][ty*TM+i];
            #pragma unroll
            for (int j=0;j<TN;j++) b[j]=Bs[kk][tx*TN+j];
            #pragma unroll
            for (int i=0;i<TM;i++)
                #pragma unroll
                for (int j=0;j<TN;j++)
                    acc[i][j] = fmaf(a[i], b[j], acc[i][j]);
        }
        __syncthreads();
    }
    #pragma unroll
    for (int i=0;i<TM;i++){
        int m = row0 + ty*TM + i;
        if (m>=M) continue;
        #pragma unroll
        for (int j=0;j<TN;j++){
            int n = col0 + tx*TN + j;
            if (n<N) fC(m,n,acc[i][j]);
        }
    }
}

// ---------------- kernels ----------------------------------------------------

__global__ void k_zero(){
    if (threadIdx.x < En) d_cnt[threadIdx.x] = 0;
}

// per-batch mean/var over C*S elements
__global__ void k_lnstats(const float* __restrict__ x){
    const int b = blockIdx.x;
    const float* xp = x + (size_t)b*Cn*Sn;
    float s=0.f, s2=0.f;
    for (int i=threadIdx.x; i<Cn*Sn; i+=blockDim.x){ float v=xp[i]; s+=v; s2+=v*v; }
    __shared__ float sh[1024], sh2[1024];
    sh[threadIdx.x]=s; sh2[threadIdx.x]=s2;
    __syncthreads();
    for (int o=blockDim.x>>1; o>0; o>>=1){
        if (threadIdx.x<o){ sh[threadIdx.x]+=sh[threadIdx.x+o]; sh2[threadIdx.x]+=sh2[threadIdx.x+o]; }
        __syncthreads();
    }
    if (threadIdx.x==0){
        const float inv = 1.f/(float)(Cn*Sn);
        float mu = sh[0]*inv;
        float var = sh2[0]*inv - mu*mu;
        d_mu[b]=mu; d_rstd[b]=rsqrtf(var+1e-5f);
    }
}

// xn = (x-mu)*rstd*gamma + beta, transposed [b,C,S] -> [b,S,C]
__global__ void k_ln(const float* __restrict__ x, const float* __restrict__ g,
                     const float* __restrict__ be){
    __shared__ float tile[32][33];
    const int b = blockIdx.z;
    const int s0 = blockIdx.x*32, c0 = blockIdx.y*32;
    const float mu = d_mu[b], rs = d_rstd[b];
    {   // load: coalesced along s
        int s = s0+threadIdx.x, c = c0+threadIdx.y;
        if (s < Sn){
            float xv = x[((size_t)b*Cn+c)*Sn + s];
            tile[threadIdx.y][threadIdx.x] = (xv-mu)*rs*g[c*Sn+s] + be[c*Sn+s];
        }
    }
    __syncthreads();
    {   // store: coalesced along c
        int s = s0+threadIdx.y, c = c0+threadIdx.x;
        if (s < Sn)
            d_tok[((size_t)b*Sn+s)*Cn + c] = tile[threadIdx.x][threadIdx.y];
    }
}

// qkv = tok @ w_qkv ; scatter into q/k/v [b,h,s,d]
__global__ void k_qkv(const float* __restrict__ wqkv){
    gemm_core<128,128,8,8,8,false>(NTOK, 3*Cn, Cn,
        [=] (int m,int k){ return d_tok[(size_t)m*Cn+k]; },
        [=] (int k,int n){ return wqkv[(size_t)k*3*Cn+n]; },
        [=] (int m,int n,float v){
            int b=m/Sn, s=m%Sn;
            int which=n/Cn, r=n%Cn, h=r/Dn, dd=r%Dn;
            float* dst = (which==0)? d_q : (which==1)? d_k : d_v;
            dst[(((size_t)b*Hn+h)*Sn+s)*Dn+dd] = v;
        });
}

// scores[bh] = Q @ K^T   (no 1/sqrt(d) scaling, per reference)
__global__ void k_scores(){
    const int bh = blockIdx.z;
    const float* Q  = d_q + (size_t)bh*Sn*Dn;
    const float* Kp = d_k + (size_t)bh*Sn*Dn;
    float* Sc = d_sc + (size_t)bh*Sn*Sn;
    gemm_core<128,128,8,8,8,true>(Sn,Sn,Dn,
        [=] (int m,int k){ return Q[m*Dn+k]; },
        [=] (int k,int n){ return Kp[n*Dn+k]; },
        [=] (int m,int n,float v){ Sc[(size_t)m*Sn+n]=v; });
}

// row softmax, warp per row
__global__ void k_softmax(){
    const int row = blockIdx.x*4 + threadIdx.y;
    if (row >= Bn*Hn*Sn) return;
    float* p = d_sc + (size_t)row*Sn;
    const int lane = threadIdx.x;
    float mx = -1e30f;
    for (int i=lane;i<Sn;i+=32) mx = fmaxf(mx, p[i]);
    #pragma unroll
    for (int o=16;o>0;o>>=1) mx = fmaxf(mx, __shfl_xor_sync(0xffffffffu, mx, o));
    float sum = 0.f;
    for (int i=lane;i<Sn;i+=32){ float e=expf(p[i]-mx); p[i]=e; sum+=e; }
    #pragma unroll
    for (int o=16;o>0;o>>=1) sum += __shfl_xor_sync(0xffffffffu, sum, o);
    const float inv = 1.f/sum;
    for (int i=lane;i<Sn;i+=32) p[i] *= inv;
}

// ctx[bh] = P @ V, scattered to [b,s, h*96+d]
__global__ void k_ctx(){
    const int bh = blockIdx.z;
    const int b = bh/Hn, h = bh%Hn;
    const float* Sc = d_sc + (size_t)bh*Sn*Sn;
    const float* V  = d_v  + (size_t)bh*Sn*Dn;
    gemm_core<128,96,8,8,6,false>(Sn,Dn,Sn,
        [=] (int m,int k){ return Sc[(size_t)m*Sn+k]; },
        [=] (int k,int n){ return V[k*Dn+n]; },
        [=] (int m,int n,float v){ d_ctx[((size_t)b*Sn+m)*Cn + h*Dn + n] = v; });
}

// x2 = ctx @ w_out + x   (x read transposed), stored [b,s,c]
__global__ void k_oproj(const float* __restrict__ wout, const float* __restrict__ x){
    gemm_core<128,128,8,8,8,false>(NTOK,Cn,Cn,
        [=] (int m,int k){ return d_ctx[(size_t)m*Cn+k]; },
        [=] (int k,int n){ return wout[(size_t)k*Cn+n]; },
        [=] (int m,int n,float v){
            int b=m/Sn, s=m%Sn;
            d_x2[(size_t)m*Cn+n] = v + x[((size_t)b*Cn+n)*Sn+s];
        });
}

// gate: logits, softmax3, argmax (first-max tie-break), mg value
__global__ void k_gate(const float* __restrict__ wg, const float* __restrict__ bg){
    const int t = blockIdx.x*8 + threadIdx.y;
    if (t >= NTOK) return;
    const int lane = threadIdx.x;
    const float* xr = d_x2 + (size_t)t*Cn;
    float a0=0.f,a1=0.f,a2=0.f;
    for (int c=lane;c<Cn;c+=32){
        float v = xr[c];
        a0 = fmaf(v, wg[c*3+0], a0);
        a1 = fmaf(v, wg[c*3+1], a1);
        a2 = fmaf(v, wg[c*3+2], a2);
    }
    #pragma unroll
    for (int o=16;o>0;o>>=1){
        a0 += __shfl_xor_sync(0xffffffffu,a0,o);
        a1 += __shfl_xor_sync(0xffffffffu,a1,o);
        a2 += __shfl_xor_sync(0xffffffffu,a2,o);
    }
    if (lane==0){
        a0+=bg[0]; a1+=bg[1]; a2+=bg[2];
        int am=0; float m=a0;
        if (a1>m){m=a1;am=1;}
        if (a2>m){m=a2;am=2;}
        float e0=expf(a0-m), e1=expf(a1-m), e2=expf(a2-m);
        float sum=e0+e1+e2;
        float pm = ((am==0)?e0:(am==1)?e1:e2)/sum;
        d_eid[t]=am; d_mg[t]=pm;
    }
}

// denom[s,e] = sum_b mg (deterministic order, matches jnp.sum over axis 0)
__global__ void k_denom(){
    const int i = blockIdx.x*256 + threadIdx.x;
    if (i >= Sn*En) return;
    const int s = i/En, e = i%En;
    float acc = 0.f;
    #pragma unroll
    for (int b=0;b<Bn;b++){
        int t = b*Sn+s;
        if (d_eid[t]==e) acc += d_mg[t];
    }
    d_denom[i] = acc;
}

// gate score + expert bucket lists
__global__ void k_gs(){
    const int t = blockIdx.x*256 + threadIdx.x;
    if (t >= NTOK) return;
    const int e = d_eid[t], s = t % Sn;
    d_gs[t] = d_mg[t] / (d_denom[s*En+e] + 1e-6f) * (float)Bn;
    int pos = atomicAdd(&d_cnt[e], 1);
    d_list[e*NTOK + pos] = t;
}

// expert FFN layer 1 + exact GELU (gathered rows). Grid sized worst-case;
// blocks beyond the live count return immediately.
__global__ void k_moe1(const float* __restrict__ w1, const float* __restrict__ b1){
    const int e = blockIdx.z;
    const int cnt = d_cnt[e];
    const int* lst = d_list + e*NTOK;
    const float* W = w1 + (size_t)e*Cn*HIDn;
    gemm_core<128,128,8,8,8,false>(cnt,HIDn,Cn,
        [=] (int m,int k){ return d_x2[(size_t)lst[m]*Cn+k]; },
        [=] (int k,int n){ return W[(size_t)k*HIDn+n]; },
        [=] (int m,int n,float v){
            float xg = v + b1[e*HIDn+n];
            float gl = 0.5f*xg*(1.f + erff(xg*0.70710678118654752f));
            d_hmid[(size_t)lst[m]*HIDn+n] = gl;
        });
}

// expert FFN layer 2, scaled by gate score, scattered by token
__global__ void k_moe2(const float* __restrict__ w2, const float* __restrict__ b2){
    const int e = blockIdx.z;
    const int cnt = d_cnt[e];
    const int* lst = d_list + e*NTOK;
    const float* W = w2 + (size_t)e*HIDn*Cn;
    gemm_core<128,128,8,8,8,false>(cnt,Cn,HIDn,
        [=] (int m,int k){ return d_hmid[(size_t)lst[m]*HIDn+k]; },
        [=] (int k,int n){ return W[(size_t)k*Cn+n]; },
        [=] (int m,int n,float v){
            int t = lst[m];
            d_moe[(size_t)t*Cn+n] = (v + b2[e*Cn+n]) * d_gs[t];
        });
}

// out[b,c,s] = x2[b,s,c] + moe[b,s,c]  (tiled transpose)
__global__ void k_final(float* __restrict__ out){
    __shared__ float tile[32][33];
    const int b = blockIdx.z;
    const int s0 = blockIdx.x*32, c0 = blockIdx.y*32;
    {   // load coalesced along c
        int s = s0+threadIdx.y, c = c0+threadIdx.x;
        if (s < Sn){
            size_t idx = ((size_t)b*Sn+s)*Cn + c;
            tile[threadIdx.y][threadIdx.x] = d_x2[idx] + d_moe[idx];
        }
    }
    __syncthreads();
    {   // store coalesced along s
        int s = s0+threadIdx.x, c = c0+threadIdx.y;
        if (s < Sn)
            out[((size_t)b*Cn+c)*Sn + s] = tile[threadIdx.x][threadIdx.y];
    }
}

// ---------------- launch ------------------------------------------------------
extern "C" void kernel_launch(void* const* d_in, const int* in_sizes, int n_in,
                              void* d_out, int out_size){
    const float* x     = (const float*)d_in[0];
    const float* gam   = (const float*)d_in[1];
    const float* bet   = (const float*)d_in[2];
    const float* wqkv  = (const float*)d_in[3];
    const float* wout  = (const float*)d_in[4];
    const float* wgate = (const float*)d_in[5];
    const float* bgate = (const float*)d_in[6];
    const float* w1    = (const float*)d_in[7];
    const float* b1    = (const float*)d_in[8];
    const float* w2    = (const float*)d_in[9];
    const float* b2    = (const float*)d_in[10];
    float* out = (float*)d_out;

    k_zero<<<1,32>>>();
    k_lnstats<<<Bn,1024>>>(x);
    k_ln<<<dim3(23,24,Bn), dim3(32,32)>>>(x, gam, bet);
    k_qkv<<<dim3((NTOK+127)/128, (3*Cn)/128), 256>>>(wqkv);
    k_scores<<<dim3(6,6,Bn*Hn), 256>>>();
    k_softmax<<<(Bn*Hn*Sn)/4, dim3(32,4)>>>();
    k_ctx<<<dim3(6,1,Bn*Hn), 256>>>();
    k_oproj<<<dim3((NTOK+127)/128, Cn/128), 256>>>(wout, x);
    k_gate<<<NTOK/8, dim3(32,8)>>>(wgate, bgate);
    k_denom<<<(Sn*En+255)/256, 256>>>();
    k_gs<<<(NTOK+255)/256, 256>>>();
    k_moe1<<<dim3((NTOK+127)/128, HIDn/128, En), 256>>>(w1, b1);
    k_moe2<<<dim3((NTOK+127)/128, Cn/128, En), 256>>>(w2, b2);
    k_final<<<dim3(23,24,Bn), dim3(32,32)>>>(out);
}

// round 2
// speedup vs baseline: 1.8037x; 1.8037x over previous
#include <cuda_runtime.h>
#include <math.h>
#include <stdint.h>

// Problem constants
#define Bn   16
#define Cn   768
#define Sn   729
#define Hn   8
#define Dn   96
#define En   3
#define HIDn 3072
#define NTOK (Bn*Sn)          // 11664

// ---------------- scratch (device globals; no allocation allowed) -----------
__device__ float d_mu[Bn], d_rstd[Bn];
__device__ float d_tok[(size_t)NTOK*Cn];                 // xn, [b,s,c]
__device__ float d_q[(size_t)Bn*Hn*Sn*Dn];
__device__ float d_k[(size_t)Bn*Hn*Sn*Dn];
__device__ float d_v[(size_t)Bn*Hn*Sn*Dn];
__device__ float d_sc[(size_t)Bn*Hn*Sn*Sn];              // scores / probs, 272MB
__device__ float d_ctx[(size_t)NTOK*Cn];
__device__ float d_x2[(size_t)NTOK*Cn];                  // x + attn_out, [b,s,c]
__device__ int   d_eid[NTOK];
__device__ float d_mg[NTOK];
__device__ float d_gs[NTOK];
__device__ float d_denom[Sn*En];
__device__ int   d_cnt[En];
__device__ int   d_list[En*NTOK];
__device__ float d_hmid[(size_t)NTOK*HIDn];              // 143MB, indexed by token
__device__ float d_moe[(size_t)NTOK*Cn];

// ---------------- tf32 tensor-core GEMM core --------------------------------
__device__ __forceinline__ uint32_t f2tf32(float f){
    uint32_t u;
    asm("cvt.rna.tf32.f32 %0, %1;" : "=r"(u) : "f"(f));
    return u;
}

__device__ __forceinline__ void mma_tf32(float* c, const uint32_t* a, const uint32_t* b){
    asm volatile(
        "mma.sync.aligned.m16n8k8.row.col.f32.tf32.tf32.f32 "
        "{%0,%1,%2,%3}, {%4,%5,%6,%7}, {%8,%9}, {%0,%1,%2,%3};\n"
        : "+f"(c[0]), "+f"(c[1]), "+f"(c[2]), "+f"(c[3])
        : "r"(a[0]), "r"(a[1]), "r"(a[2]), "r"(a[3]), "r"(b[0]), "r"(b[1]));
}

// C[m,n] = sum_k A(m,k)*B(k,n), fp32 accum, tf32 multiply.
// Block tile 128x128x16, 256 threads, warp grid 2x4, warp tile 64x32.
// BKF=true: B loader is K-fast in memory (loads coalesce along k).
template<bool BKF, class FA,class FB,class FC>
__device__ __forceinline__ void tgemm(int M,int N,int K, FA fA, FB fB, FC fC){
    constexpr int BM=128, BN=128, BK=16, PAD=8;   // 136 % 32 == 8 -> conflict-free frags
    __shared__ uint32_t As[BK][BM+PAD];
    __shared__ uint32_t Bs[BK][BN+PAD];
    const int tid  = threadIdx.x;
    const int wid  = tid >> 5, lane = tid & 31;
    const int wy   = wid >> 2, wx   = wid & 3;    // 2 x 4 warps
    const int gid  = lane >> 2, tig = lane & 3;
    const int row0 = blockIdx.x * BM;
    const int col0 = blockIdx.y * BN;
    if (row0 >= M) return;

    float acc[4][4][4];
    #pragma unroll
    for (int i=0;i<4;i++)
        #pragma unroll
        for (int j=0;j<4;j++)
            #pragma unroll
            for (int r=0;r<4;r++) acc[i][j][r]=0.f;

    for (int k0=0; k0<K; k0+=BK){
        // stage A: coalesced along k
        #pragma unroll
        for (int l=tid; l<BM*BK; l+=256){
            int kk = l % BK, mm = l / BK;
            int m = row0+mm, k = k0+kk;
            As[kk][mm] = (m<M && k<K) ? f2tf32(fA(m,k)) : 0u;
        }
        // stage B
        #pragma unroll
        for (int l=tid; l<BN*BK; l+=256){
            int kk, nn;
            if (BKF){ kk = l % BK; nn = l / BK; }
            else    { nn = l % BN; kk = l / BN; }
            int k = k0+kk, n = col0+nn;
            Bs[kk][nn] = (k<K && n<N) ? f2tf32(fB(k,n)) : 0u;
        }
        __syncthreads();

        #pragma unroll
        for (int ks=0; ks<BK; ks+=8){
            uint32_t aF[4][4], bF[4][2];
            #pragma unroll
            for (int mt=0; mt<4; mt++){
                int m = wy*64 + mt*16 + gid;
                aF[mt][0] = As[ks+tig  ][m  ];
                aF[mt][1] = As[ks+tig  ][m+8];
                aF[mt][2] = As[ks+tig+4][m  ];
                aF[mt][3] = As[ks+tig+4][m+8];
            }
            #pragma unroll
            for (int nt=0; nt<4; nt++){
                int n = wx*32 + nt*8 + gid;
                bF[nt][0] = Bs[ks+tig  ][n];
                bF[nt][1] = Bs[ks+tig+4][n];
            }
            #pragma unroll
            for (int mt=0; mt<4; mt++)
                #pragma unroll
                for (int nt=0; nt<4; nt++)
                    mma_tf32(acc[mt][nt], aF[mt], bF[nt]);
        }
        __syncthreads();
    }

    // epilogue: c0/c1 -> (gid, 2*tig{,+1}); c2/c3 -> (gid+8, 2*tig{,+1})
    #pragma unroll
    for (int mt=0; mt<4; mt++){
        #pragma unroll
        for (int nt=0; nt<4; nt++){
            int mB = row0 + wy*64 + mt*16;
            int nB = col0 + wx*32 + nt*8;
            int r0 = mB + gid, r1 = mB + gid + 8;
            int c0 = nB + 2*tig, c1 = c0 + 1;
            if (r0 < M){
                if (c0 < N) fC(r0, c0, acc[mt][nt][0]);
                if (c1 < N) fC(r0, c1, acc[mt][nt][1]);
            }
            if (r1 < M){
                if (c0 < N) fC(r1, c0, acc[mt][nt][2]);
                if (c1 < N) fC(r1, c1, acc[mt][nt][3]);
            }
        }
    }
}

// ---------------- kernels ----------------------------------------------------

__global__ void k_zero(){
    if (threadIdx.x < En) d_cnt[threadIdx.x] = 0;
}

// per-batch mean/var over C*S elements
__global__ void k_lnstats(const float* __restrict__ x){
    const int b = blockIdx.x;
    const float* xp = x + (size_t)b*Cn*Sn;
    float s=0.f, s2=0.f;
    for (int i=threadIdx.x; i<Cn*Sn; i+=blockDim.x){ float v=xp[i]; s+=v; s2+=v*v; }
    __shared__ float sh[1024], sh2[1024];
    sh[threadIdx.x]=s; sh2[threadIdx.x]=s2;
    __syncthreads();
    for (int o=blockDim.x>>1; o>0; o>>=1){
        if (threadIdx.x<o){ sh[threadIdx.x]+=sh[threadIdx.x+o]; sh2[threadIdx.x]+=sh2[threadIdx.x+o]; }
        __syncthreads();
    }
    if (threadIdx.x==0){
        const float inv = 1.f/(float)(Cn*Sn);
        float mu = sh[0]*inv;
        float var = sh2[0]*inv - mu*mu;
        d_mu[b]=mu; d_rstd[b]=rsqrtf(var+1e-5f);
    }
}

// xn = (x-mu)*rstd*gamma + beta, transposed [b,C,S] -> [b,S,C]
__global__ void k_ln(const float* __restrict__ x, const float* __restrict__ g,
                     const float* __restrict__ be){
    __shared__ float tile[32][33];
    const int b = blockIdx.z;
    const int s0 = blockIdx.x*32, c0 = blockIdx.y*32;
    const float mu = d_mu[b], rs = d_rstd[b];
    {
        int s = s0+threadIdx.x, c = c0+threadIdx.y;
        if (s < Sn){
            float xv = x[((size_t)b*Cn+c)*Sn + s];
            tile[threadIdx.y][threadIdx.x] = (xv-mu)*rs*g[c*Sn+s] + be[c*Sn+s];
        }
    }
    __syncthreads();
    {
        int s = s0+threadIdx.y, c = c0+threadIdx.x;
        if (s < Sn)
            d_tok[((size_t)b*Sn+s)*Cn + c] = tile[threadIdx.x][threadIdx.y];
    }
}

// qkv = tok @ w_qkv ; scatter into q/k/v [b,h,s,d]
__global__ void __launch_bounds__(256) k_qkv(const float* __restrict__ wqkv){
    tgemm<false>(NTOK, 3*Cn, Cn,
        [=] (int m,int k){ return d_tok[(size_t)m*Cn+k]; },
        [=] (int k,int n){ return wqkv[(size_t)k*3*Cn+n]; },
        [=] (int m,int n,float v){
            int b=m/Sn, s=m%Sn;
            int which=n/Cn, r=n%Cn, h=r/Dn, dd=r%Dn;
            float* dst = (which==0)? d_q : (which==1)? d_k : d_v;
            dst[(((size_t)b*Hn+h)*Sn+s)*Dn+dd] = v;
        });
}

// scores[bh] = Q @ K^T   (no 1/sqrt(d) scaling, per reference)
__global__ void __launch_bounds__(256) k_scores(){
    const int bh = blockIdx.z;
    const float* Q  = d_q + (size_t)bh*Sn*Dn;
    const float* Kp = d_k + (size_t)bh*Sn*Dn;
    float* Sc = d_sc + (size_t)bh*Sn*Sn;
    tgemm<true>(Sn,Sn,Dn,
        [=] (int m,int k){ return Q[m*Dn+k]; },
        [=] (int k,int n){ return Kp[n*Dn+k]; },
        [=] (int m,int n,float v){ Sc[(size_t)m*Sn+n]=v; });
}

// row softmax, warp per row
__global__ void k_softmax(){
    const int row = blockIdx.x*4 + threadIdx.y;
    if (row >= Bn*Hn*Sn) return;
    float* p = d_sc + (size_t)row*Sn;
    const int lane = threadIdx.x;
    float mx = -1e30f;
    for (int i=lane;i<Sn;i+=32) mx = fmaxf(mx, p[i]);
    #pragma unroll
    for (int o=16;o>0;o>>=1) mx = fmaxf(mx, __shfl_xor_sync(0xffffffffu, mx, o));
    float sum = 0.f;
    for (int i=lane;i<Sn;i+=32){ float e=expf(p[i]-mx); p[i]=e; sum+=e; }
    #pragma unroll
    for (int o=16;o>0;o>>=1) sum += __shfl_xor_sync(0xffffffffu, sum, o);
    const float inv = 1.f/sum;
    for (int i=lane;i<Sn;i+=32) p[i] *= inv;
}

// ctx[bh] = P @ V, scattered to [b,s, h*96+d]
__global__ void __launch_bounds__(256) k_ctx(){
    const int bh = blockIdx.z;
    const int b = bh/Hn, h = bh%Hn;
    const float* Sc = d_sc + (size_t)bh*Sn*Sn;
    const float* V  = d_v  + (size_t)bh*Sn*Dn;
    tgemm<false>(Sn,Dn,Sn,
        [=] (int m,int k){ return Sc[(size_t)m*Sn+k]; },
        [=] (int k,int n){ return V[k*Dn+n]; },
        [=] (int m,int n,float v){ d_ctx[((size_t)b*Sn+m)*Cn + h*Dn + n] = v; });
}

// x2 = ctx @ w_out + x   (x read transposed), stored [b,s,c]
__global__ void __launch_bounds__(256) k_oproj(const float* __restrict__ wout,
                                               const float* __restrict__ x){
    tgemm<false>(NTOK,Cn,Cn,
        [=] (int m,int k){ return d_ctx[(size_t)m*Cn+k]; },
        [=] (int k,int n){ return wout[(size_t)k*Cn+n]; },
        [=] (int m,int n,float v){
            int b=m/Sn, s=m%Sn;
            d_x2[(size_t)m*Cn+n] = v + x[((size_t)b*Cn+n)*Sn+s];
        });
}

// gate: logits, softmax3, argmax (first-max tie-break), mg value
__global__ void k_gate(const float* __restrict__ wg, const float* __restrict__ bg){
    const int t = blockIdx.x*8 + threadIdx.y;
    if (t >= NTOK) return;
    const int lane = threadIdx.x;
    const float* xr = d_x2 + (size_t)t*Cn;
    float a0=0.f,a1=0.f,a2=0.f;
    for (int c=lane;c<Cn;c+=32){
        float v = xr[c];
        a0 = fmaf(v, wg[c*3+0], a0);
        a1 = fmaf(v, wg[c*3+1], a1);
        a2 = fmaf(v, wg[c*3+2], a2);
    }
    #pragma unroll
    for (int o=16;o>0;o>>=1){
        a0 += __shfl_xor_sync(0xffffffffu,a0,o);
        a1 += __shfl_xor_sync(0xffffffffu,a1,o);
        a2 += __shfl_xor_sync(0xffffffffu,a2,o);
    }
    if (lane==0){
        a0+=bg[0]; a1+=bg[1]; a2+=bg[2];
        int am=0; float m=a0;
        if (a1>m){m=a1;am=1;}
        if (a2>m){m=a2;am=2;}
        float e0=expf(a0-m), e1=expf(a1-m), e2=expf(a2-m);
        float sum=e0+e1+e2;
        float pm = ((am==0)?e0:(am==1)?e1:e2)/sum;
        d_eid[t]=am; d_mg[t]=pm;
    }
}

// denom[s,e] = sum_b mg (deterministic order, matches jnp.sum over axis 0)
__global__ void k_denom(){
    const int i = blockIdx.x*256 + threadIdx.x;
    if (i >= Sn*En) return;
    const int s = i/En, e = i%En;
    float acc = 0.f;
    #pragma unroll
    for (int b=0;b<Bn;b++){
        int t = b*Sn+s;
        if (d_eid[t]==e) acc += d_mg[t];
    }
    d_denom[i] = acc;
}

// gate score + expert bucket lists
__global__ void k_gs(){
    const int t = blockIdx.x*256 + threadIdx.x;
    if (t >= NTOK) return;
    const int e = d_eid[t], s = t % Sn;
    d_gs[t] = d_mg[t] / (d_denom[s*En+e] + 1e-6f) * (float)Bn;
    int pos = atomicAdd(&d_cnt[e], 1);
    d_list[e*NTOK + pos] = t;
}

// expert FFN layer 1 + exact GELU (gathered rows)
__global__ void __launch_bounds__(256) k_moe1(const float* __restrict__ w1,
                                              const float* __restrict__ b1){
    const int e = blockIdx.z;
    const int cnt = d_cnt[e];
    const int* lst = d_list + e*NTOK;
    const float* W = w1 + (size_t)e*Cn*HIDn;
    tgemm<false>(cnt,HIDn,Cn,
        [=] (int m,int k){ return d_x2[(size_t)lst[m]*Cn+k]; },
        [=] (int k,int n){ return W[(size_t)k*HIDn+n]; },
        [=] (int m,int n,float v){
            float xg = v + b1[e*HIDn+n];
            float gl = 0.5f*xg*(1.f + erff(xg*0.70710678118654752f));
            d_hmid[(size_t)lst[m]*HIDn+n] = gl;
        });
}

// expert FFN layer 2, scaled by gate score, scattered by token
__global__ void __launch_bounds__(256) k_moe2(const float* __restrict__ w2,
                                              const float* __restrict__ b2){
    const int e = blockIdx.z;
    const int cnt = d_cnt[e];
    const int* lst = d_list + e*NTOK;
    const float* W = w2 + (size_t)e*HIDn*Cn;
    tgemm<false>(cnt,Cn,HIDn,
        [=] (int m,int k){ return d_hmid[(size_t)lst[m]*HIDn+k]; },
        [=] (int k,int n){ return W[(size_t)k*Cn+n]; },
        [=] (int m,int n,float v){
            int t = lst[m];
            d_moe[(size_t)t*Cn+n] = (v + b2[e*Cn+n]) * d_gs[t];
        });
}

// out[b,c,s] = x2[b,s,c] + moe[b,s,c]  (tiled transpose)
__global__ void k_final(float* __restrict__ out){
    __shared__ float tile[32][33];
    const int b = blockIdx.z;
    const int s0 = blockIdx.x*32, c0 = blockIdx.y*32;
    {
        int s = s0+threadIdx.y, c = c0+threadIdx.x;
        if (s < Sn){
            size_t idx = ((size_t)b*Sn+s)*Cn + c;
            tile[threadIdx.y][threadIdx.x] = d_x2[idx] + d_moe[idx];
        }
    }
    __syncthreads();
    {
        int s = s0+threadIdx.x, c = c0+threadIdx.y;
        if (s < Sn)
            out[((size_t)b*Cn+c)*Sn + s] = tile[threadIdx.x][threadIdx.y];
    }
}

// ---------------- launch ------------------------------------------------------
extern "C" void kernel_launch(void* const* d_in, const int* in_sizes, int n_in,
                              void* d_out, int out_size){
    const float* x     = (const float*)d_in[0];
    const float* gam   = (const float*)d_in[1];
    const float* bet   = (const float*)d_in[2];
    const float* wqkv  = (const float*)d_in[3];
    const float* wout  = (const float*)d_in[4];
    const float* wgate = (const float*)d_in[5];
    const float* bgate = (const float*)d_in[6];
    const float* w1    = (const float*)d_in[7];
    const float* b1    = (const float*)d_in[8];
    const float* w2    = (const float*)d_in[9];
    const float* b2    = (const float*)d_in[10];
    float* out = (float*)d_out;

    k_zero<<<1,32>>>();
    k_lnstats<<<Bn,1024>>>(x);
    k_ln<<<dim3(23,24,Bn), dim3(32,32)>>>(x, gam, bet);
    k_qkv<<<dim3((NTOK+127)/128, (3*Cn)/128), 256>>>(wqkv);
    k_scores<<<dim3(6,6,Bn*Hn), 256>>>();
    k_softmax<<<(Bn*Hn*Sn)/4, dim3(32,4)>>>();
    k_ctx<<<dim3(6,1,Bn*Hn), 256>>>();
    k_oproj<<<dim3((NTOK+127)/128, Cn/128), 256>>>(wout, x);
    k_gate<<<NTOK/8, dim3(32,8)>>>(wgate, bgate);
    k_denom<<<(Sn*En+255)/256, 256>>>();
    k_gs<<<(NTOK+255)/256, 256>>>();
    k_moe1<<<dim3((NTOK+127)/128, HIDn/128, En), 256>>>(w1, b1);
    k_moe2<<<dim3((NTOK+127)/128, Cn/128, En), 256>>>(w2, b2);
    k_final<<<dim3(23,24,Bn), dim3(32,32)>>>(out);
}

// round 3
// speedup vs baseline: 5.4831x; 3.0399x over previous
#include <cuda_runtime.h>
#include <math.h>
#include <stdint.h>

// Problem constants
#define Bn   16
#define Cn   768
#define Sn   729
#define Hn   8
#define Dn   96
#define En   3
#define HIDn 3072
#define NTOK (Bn*Sn)          // 11664
#define SP   736              // padded scores row stride (16B-aligned rows)

// ---------------- scratch (device globals; no allocation allowed) -----------
__device__ __align__(256) float d_mu[Bn], d_rstd[Bn];
__device__ __align__(256) float d_part[Bn*64*2];
__device__ __align__(256) float d_tok[(size_t)NTOK*Cn];
__device__ __align__(256) float d_q[(size_t)Bn*Hn*Sn*Dn];
__device__ __align__(256) float d_k[(size_t)Bn*Hn*Sn*Dn];
__device__ __align__(256) float d_v[(size_t)Bn*Hn*Sn*Dn];
__device__ __align__(256) float d_sc[(size_t)Bn*Hn*Sn*SP];   // padded rows
__device__ __align__(256) float d_ctx[(size_t)NTOK*Cn];
__device__ __align__(256) float d_x2[(size_t)NTOK*Cn];
__device__ int   d_eid[NTOK];
__device__ float d_mg[NTOK];
__device__ float d_gs[NTOK];
__device__ float d_denom[Sn*En];
__device__ int   d_cnt[En];
__device__ int   d_list[En*NTOK];
__device__ __align__(256) float d_hmid[(size_t)NTOK*HIDn];
__device__ __align__(256) float d_moe[(size_t)NTOK*Cn];

// ---------------- primitives -------------------------------------------------
__device__ __forceinline__ uint32_t f2tf32(float f){
    uint32_t u;
    asm("cvt.rna.tf32.f32 %0, %1;" : "=r"(u) : "f"(f));
    return u;
}
__device__ __forceinline__ void mma_tf32(float* c, const uint32_t* a, const uint32_t* b){
    asm volatile(
        "mma.sync.aligned.m16n8k8.row.col.f32.tf32.tf32.f32 "
        "{%0,%1,%2,%3}, {%4,%5,%6,%7}, {%8,%9}, {%0,%1,%2,%3};\n"
        : "+f"(c[0]), "+f"(c[1]), "+f"(c[2]), "+f"(c[3])
        : "r"(a[0]), "r"(a[1]), "r"(a[2]), "r"(a[3]), "r"(b[0]), "r"(b[1]));
}
__device__ __forceinline__ void cp16(uint32_t dst, const void* src, int sb){
    asm volatile("cp.async.cg.shared.global [%0], [%1], 16, %2;\n"
                 :: "r"(dst), "l"(src), "r"(sb));
}
__device__ __forceinline__ void cpcommit(){ asm volatile("cp.async.commit_group;\n"); }
template<int NW> __device__ __forceinline__ void cpwait(){
    asm volatile("cp.async.wait_group %0;\n" :: "n"(NW));
}

// ---------------- tf32 tensor-core GEMM core (cp.async double-buffered) -----
// Block tile 128x128x32, 256 threads, warp grid 2x4, warp tile 64x32.
// Loaders return global ADDRESSES: fA(m,k)->&A[m][k] (k-contig, 16B-aligned at
// k%4==0), fB(k,n): BKF=false -> n-contig; BKF=true -> k-contig (B^T layout).
// A tile (and BKF B tile) stored k-fast with SW128 xor swizzle; B k-major tile
// stored [32][136] (pad 8 -> conflict-free frag LDS).
template<bool BKF, class FA,class FB,class FC>
__device__ __forceinline__ void tgemm(int M,int N,int K, FA fA, FB fB, FC fC){
    constexpr int BM=128, BN=128, BK=32;
    extern __shared__ float sm_[];
    float* Ab = sm_;            // 2 * 4096 floats
    float* Bb = sm_ + 8192;     // 2 * 4352 floats
    const int tid = threadIdx.x;
    const int wid = tid >> 5, lane = tid & 31;
    const int wy  = wid >> 2, wx = wid & 3;
    const int gid = lane >> 2, tig = lane & 3;
    const int row0 = blockIdx.x * BM;
    const int col0 = blockIdx.y * BN;
    if (row0 >= M) return;
    const uint32_t sA = (uint32_t)__cvta_generic_to_shared(Ab);
    const uint32_t sB = (uint32_t)__cvta_generic_to_shared(Bb);

    float acc[4][4][4];
    #pragma unroll
    for (int i=0;i<4;i++)
        #pragma unroll
        for (int j=0;j<4;j++)
            #pragma unroll
            for (int r=0;r<4;r++) acc[i][j][r]=0.f;

    auto stage = [&](int buf, int k0){
        uint32_t aB = sA + (uint32_t)buf*4096u*4u;
        #pragma unroll
        for (int i=0;i<4;i++){
            int v = tid + i*256, m = v >> 3, kv = v & 7;
            int gm = row0 + m, kg = k0 + kv*4;
            int sb = 0, ka = 0, ma = row0;
            if (gm < M){
                ma = gm;
                int rem = K - kg;
                if (rem > 0){ sb = rem >= 4 ? 16 : rem*4; ka = kg; }
            }
            cp16(aB + (uint32_t)((m<<5) + ((kv ^ (m&7))<<2))*4u, fA(ma, ka), sb);
        }
        uint32_t bB = sB + (uint32_t)buf*4352u*4u;
        if (!BKF){
            #pragma unroll
            for (int i=0;i<4;i++){
                int v = tid + i*256, kk = v >> 5, nv = v & 31;
                int kg = k0 + kk, ng = col0 + nv*4;
                int sb = 0, ka = 0, na = col0;
                if (kg < K){
                    ka = kg;
                    int rem = N - ng;
                    if (rem > 0){ sb = rem >= 4 ? 16 : rem*4; na = ng; }
                }
                cp16(bB + (uint32_t)(kk*136 + nv*4)*4u, fB(ka, na), sb);
            }
        } else {
            #pragma unroll
            for (int i=0;i<4;i++){
                int v = tid + i*256, n = v >> 3, kv = v & 7;
                int gn = col0 + n, kg = k0 + kv*4;
                int sb = 0, ka = 0, na = col0;
                if (gn < N){
                    na = gn;
                    int rem = K - kg;
                    if (rem > 0){ sb = rem >= 4 ? 16 : rem*4; ka = kg; }
                }
                cp16(bB + (uint32_t)((n<<5) + ((kv ^ (n&7))<<2))*4u, fB(ka, na), sb);
            }
        }
        cpcommit();
    };

    const int nk = (K + BK - 1) / BK;
    stage(0, 0);
    for (int t=0; t<nk; t++){
        const int buf = t & 1;
        if (t+1 < nk){ stage(buf^1, (t+1)*BK); cpwait<1>(); }
        else          { cpwait<0>(); }
        __syncthreads();
        const float* A = Ab + buf*4096;
        const float* B = Bb + buf*4352;
        #pragma unroll
        for (int ks=0; ks<BK; ks+=8){
            uint32_t aF[4][4], bF[4][2];
            const int k0e = ks + tig, k1e = ks + tig + 4;
            #pragma unroll
            for (int mt=0; mt<4; mt++){
                int m  = wy*64 + mt*16 + gid;
                int m8 = m + 8;
                aF[mt][0] = f2tf32(A[(m <<5) + (((k0e>>2)^(m &7))<<2) + (k0e&3)]);
                aF[mt][1] = f2tf32(A[(m8<<5) + (((k0e>>2)^(m8&7))<<2) + (k0e&3)]);
                aF[mt][2] = f2tf32(A[(m <<5) + (((k1e>>2)^(m &7))<<2) + (k1e&3)]);
                aF[mt][3] = f2tf32(A[(m8<<5) + (((k1e>>2)^(m8&7))<<2) + (k1e&3)]);
            }
            #pragma unroll
            for (int nt=0; nt<4; nt++){
                int n = wx*32 + nt*8 + gid;
                if (!BKF){
                    bF[nt][0] = f2tf32(B[k0e*136 + n]);
                    bF[nt][1] = f2tf32(B[k1e*136 + n]);
                } else {
                    bF[nt][0] = f2tf32(B[(n<<5) + (((k0e>>2)^(n&7))<<2) + (k0e&3)]);
                    bF[nt][1] = f2tf32(B[(n<<5) + (((k1e>>2)^(n&7))<<2) + (k1e&3)]);
                }
            }
            #pragma unroll
            for (int mt=0; mt<4; mt++)
                #pragma unroll
                for (int nt=0; nt<4; nt++)
                    mma_tf32(acc[mt][nt], aF[mt], bF[nt]);
        }
        __syncthreads();
    }

    #pragma unroll
    for (int mt=0; mt<4; mt++){
        #pragma unroll
        for (int nt=0; nt<4; nt++){
            int mB = row0 + wy*64 + mt*16;
            int nB = col0 + wx*32 + nt*8;
            int r0 = mB + gid, r1 = mB + gid + 8;
            int c0 = nB + 2*tig, c1 = c0 + 1;
            if (r0 < M){
                if (c0 < N) fC(r0, c0, acc[mt][nt][0]);
                if (c1 < N) fC(r0, c1, acc[mt][nt][1]);
            }
            if (r1 < M){
                if (c0 < N) fC(r1, c0, acc[mt][nt][2]);
                if (c1 < N) fC(r1, c1, acc[mt][nt][3]);
            }
        }
    }
}

#define GEMM_SMEM ((8192+8704)*4)

// ---------------- kernels ----------------------------------------------------

__global__ void k_zero(){
    if (threadIdx.x < En) d_cnt[threadIdx.x] = 0;
}

// LN stats pass 1: partial sums (Bn x 64 chunks)
__global__ void k_ln1(const float* __restrict__ x){
    const int b = blockIdx.x, ch = blockIdx.y;
    const int CH = (Cn*Sn)/64;                    // 8748
    const float* xp = x + (size_t)b*Cn*Sn + (size_t)ch*CH;
    float s=0.f, s2=0.f;
    for (int i=threadIdx.x; i<CH; i+=256){ float v=xp[i]; s+=v; s2+=v*v; }
    __shared__ float sh[256], sh2[256];
    sh[threadIdx.x]=s; sh2[threadIdx.x]=s2;
    __syncthreads();
    for (int o=128; o>0; o>>=1){
        if (threadIdx.x<o){ sh[threadIdx.x]+=sh[threadIdx.x+o]; sh2[threadIdx.x]+=sh2[threadIdx.x+o]; }
        __syncthreads();
    }
    if (threadIdx.x==0){
        d_part[(b*64+ch)*2+0]=sh[0];
        d_part[(b*64+ch)*2+1]=sh2[0];
    }
}

// LN stats pass 2
__global__ void k_ln2(){
    const int b = blockIdx.x, t = threadIdx.x;   // 64 threads
    __shared__ float sh[64], sh2[64];
    sh[t]  = d_part[(b*64+t)*2+0];
    sh2[t] = d_part[(b*64+t)*2+1];
    __syncthreads();
    if (t < 32){ sh[t]+=sh[t+32]; sh2[t]+=sh2[t+32]; }
    __syncwarp();
    if (t < 32){
        float s=sh[t], s2=sh2[t];
        #pragma unroll
        for (int o=16;o>0;o>>=1){
            s  += __shfl_xor_sync(0xffffffffu, s,  o);
            s2 += __shfl_xor_sync(0xffffffffu, s2, o);
        }
        if (t==0){
            const float inv = 1.f/(float)(Cn*Sn);
            float mu = s*inv;
            float var = s2*inv - mu*mu;
            d_mu[b]=mu; d_rstd[b]=rsqrtf(var+1e-5f);
        }
    }
}

// xn = (x-mu)*rstd*gamma + beta, transposed [b,C,S] -> [b,S,C]
__global__ void k_ln(const float* __restrict__ x, const float* __restrict__ g,
                     const float* __restrict__ be){
    __shared__ float tile[32][33];
    const int b = blockIdx.z;
    const int s0 = blockIdx.x*32, c0 = blockIdx.y*32;
    const float mu = d_mu[b], rs = d_rstd[b];
    {
        int s = s0+threadIdx.x, c = c0+threadIdx.y;
        if (s < Sn){
            float xv = x[((size_t)b*Cn+c)*Sn + s];
            tile[threadIdx.y][threadIdx.x] = (xv-mu)*rs*g[c*Sn+s] + be[c*Sn+s];
        }
    }
    __syncthreads();
    {
        int s = s0+threadIdx.y, c = c0+threadIdx.x;
        if (s < Sn)
            d_tok[((size_t)b*Sn+s)*Cn + c] = tile[threadIdx.x][threadIdx.y];
    }
}

// qkv = tok @ w_qkv ; scatter into q/k/v [b,h,s,d]
__global__ void __launch_bounds__(256,2) k_qkv(const float* __restrict__ wqkv){
    tgemm<false>(NTOK, 3*Cn, Cn,
        [=] (int m,int k){ return d_tok + (size_t)m*Cn + k; },
        [=] (int k,int n){ return wqkv + (size_t)k*3*Cn + n; },
        [=] (int m,int n,float v){
            int b=m/Sn, s=m%Sn;
            int which=n/Cn, r=n%Cn, h=r/Dn, dd=r%Dn;
            float* dst = (which==0)? d_q : (which==1)? d_k : d_v;
            dst[(((size_t)b*Hn+h)*Sn+s)*Dn+dd] = v;
        });
}

// scores[bh] = Q @ K^T (no 1/sqrt(d) scaling, per reference)
__global__ void __launch_bounds__(256,2) k_scores(){
    const int bh = blockIdx.z;
    const float* Q  = d_q + (size_t)bh*Sn*Dn;
    const float* Kp = d_k + (size_t)bh*Sn*Dn;
    float* Sc = d_sc + (size_t)bh*Sn*SP;
    tgemm<true>(Sn,Sn,Dn,
        [=] (int m,int k){ return Q + (size_t)m*Dn + k; },
        [=] (int k,int n){ return Kp + (size_t)n*Dn + k; },
        [=] (int m,int n,float v){ Sc[(size_t)m*SP+n]=v; });
}

// row softmax, warp per row (padded stride)
__global__ void k_softmax(){
    const int row = blockIdx.x*4 + threadIdx.y;
    if (row >= Bn*Hn*Sn) return;
    float* p = d_sc + (size_t)row*SP;
    const int lane = threadIdx.x;
    float mx = -1e30f;
    for (int i=lane;i<Sn;i+=32) mx = fmaxf(mx, p[i]);
    #pragma unroll
    for (int o=16;o>0;o>>=1) mx = fmaxf(mx, __shfl_xor_sync(0xffffffffu, mx, o));
    float sum = 0.f;
    for (int i=lane;i<Sn;i+=32){ float e=expf(p[i]-mx); p[i]=e; sum+=e; }
    #pragma unroll
    for (int o=16;o>0;o>>=1) sum += __shfl_xor_sync(0xffffffffu, sum, o);
    const float inv = 1.f/sum;
    for (int i=lane;i<Sn;i+=32) p[i] *= inv;
}

// ctx[bh] = P @ V, scattered to [b,s, h*96+d]
__global__ void __launch_bounds__(256,2) k_ctx(){
    const int bh = blockIdx.z;
    const int b = bh/Hn, h = bh%Hn;
    const float* Sc = d_sc + (size_t)bh*Sn*SP;
    const float* V  = d_v  + (size_t)bh*Sn*Dn;
    tgemm<false>(Sn,Dn,Sn,
        [=] (int m,int k){ return Sc + (size_t)m*SP + k; },
        [=] (int k,int n){ return V + (size_t)k*Dn + n; },
        [=] (int m,int n,float v){ d_ctx[((size_t)b*Sn+m)*Cn + h*Dn + n] = v; });
}

// x2 = ctx @ w_out + x (x read transposed), stored [b,s,c]
__global__ void __launch_bounds__(256,2) k_oproj(const float* __restrict__ wout,
                                                 const float* __restrict__ x){
    tgemm<false>(NTOK,Cn,Cn,
        [=] (int m,int k){ return d_ctx + (size_t)m*Cn + k; },
        [=] (int k,int n){ return wout + (size_t)k*Cn + n; },
        [=] (int m,int n,float v){
            int b=m/Sn, s=m%Sn;
            d_x2[(size_t)m*Cn+n] = v + x[((size_t)b*Cn+n)*Sn+s];
        });
}

// gate: logits, softmax3, argmax (first-max tie-break), mg value
__global__ void k_gate(const float* __restrict__ wg, const float* __restrict__ bg){
    const int t = blockIdx.x*8 + threadIdx.y;
    if (t >= NTOK) return;
    const int lane = threadIdx.x;
    const float* xr = d_x2 + (size_t)t*Cn;
    float a0=0.f,a1=0.f,a2=0.f;
    for (int c=lane;c<Cn;c+=32){
        float v = xr[c];
        a0 = fmaf(v, wg[c*3+0], a0);
        a1 = fmaf(v, wg[c*3+1], a1);
        a2 = fmaf(v, wg[c*3+2], a2);
    }
    #pragma unroll
    for (int o=16;o>0;o>>=1){
        a0 += __shfl_xor_sync(0xffffffffu,a0,o);
        a1 += __shfl_xor_sync(0xffffffffu,a1,o);
        a2 += __shfl_xor_sync(0xffffffffu,a2,o);
    }
    if (lane==0){
        a0+=bg[0]; a1+=bg[1]; a2+=bg[2];
        int am=0; float m=a0;
        if (a1>m){m=a1;am=1;}
        if (a2>m){m=a2;am=2;}
        float e0=expf(a0-m), e1=expf(a1-m), e2=expf(a2-m);
        float sum=e0+e1+e2;
        float pm = ((am==0)?e0:(am==1)?e1:e2)/sum;
        d_eid[t]=am; d_mg[t]=pm;
    }
}

// denom[s,e] = sum_b mg (deterministic order)
__global__ void k_denom(){
    const int i = blockIdx.x*256 + threadIdx.x;
    if (i >= Sn*En) return;
    const int s = i/En, e = i%En;
    float acc = 0.f;
    #pragma unroll
    for (int b=0;b<Bn;b++){
        int t = b*Sn+s;
        if (d_eid[t]==e) acc += d_mg[t];
    }
    d_denom[i] = acc;
}

// gate score + expert bucket lists
__global__ void k_gs(){
    const int t = blockIdx.x*256 + threadIdx.x;
    if (t >= NTOK) return;
    const int e = d_eid[t], s = t % Sn;
    d_gs[t] = d_mg[t] / (d_denom[s*En+e] + 1e-6f) * (float)Bn;
    int pos = atomicAdd(&d_cnt[e], 1);
    d_list[e*NTOK + pos] = t;
}

// expert FFN layer 1 + exact GELU (gathered rows)
__global__ void __launch_bounds__(256,2) k_moe1(const float* __restrict__ w1,
                                                const float* __restrict__ b1){
    const int e = blockIdx.z;
    const int cnt = d_cnt[e];
    const int* lst = d_list + e*NTOK;
    const float* W = w1 + (size_t)e*Cn*HIDn;
    tgemm<false>(cnt,HIDn,Cn,
        [=] (int m,int k){ return d_x2 + (size_t)lst[m]*Cn + k; },
        [=] (int k,int n){ return W + (size_t)k*HIDn + n; },
        [=] (int m,int n,float v){
            float xg = v + b1[e*HIDn+n];
            float gl = 0.5f*xg*(1.f + erff(xg*0.70710678118654752f));
            d_hmid[(size_t)lst[m]*HIDn+n] = gl;
        });
}

// expert FFN layer 2, scaled by gate score, scattered by token
__global__ void __launch_bounds__(256,2) k_moe2(const float* __restrict__ w2,
                                                const float* __restrict__ b2){
    const int e = blockIdx.z;
    const int cnt = d_cnt[e];
    const int* lst = d_list + e*NTOK;
    const float* W = w2 + (size_t)e*HIDn*Cn;
    tgemm<false>(cnt,Cn,HIDn,
        [=] (int m,int k){ return d_hmid + (size_t)lst[m]*HIDn + k; },
        [=] (int k,int n){ return W + (size_t)k*Cn + n; },
        [=] (int m,int n,float v){
            int t = lst[m];
            d_moe[(size_t)t*Cn+n] = (v + b2[e*Cn+n]) * d_gs[t];
        });
}

// out[b,c,s] = x2[b,s,c] + moe[b,s,c]
__global__ void k_final(float* __restrict__ out){
    __shared__ float tile[32][33];
    const int b = blockIdx.z;
    const int s0 = blockIdx.x*32, c0 = blockIdx.y*32;
    {
        int s = s0+threadIdx.y, c = c0+threadIdx.x;
        if (s < Sn){
            size_t idx = ((size_t)b*Sn+s)*Cn + c;
            tile[threadIdx.y][threadIdx.x] = d_x2[idx] + d_moe[idx];
        }
    }
    __syncthreads();
    {
        int s = s0+threadIdx.x, c = c0+threadIdx.y;
        if (s < Sn)
            out[((size_t)b*Cn+c)*Sn + s] = tile[threadIdx.x][threadIdx.y];
    }
}

// ---------------- launch ------------------------------------------------------
extern "C" void kernel_launch(void* const* d_in, const int* in_sizes, int n_in,
                              void* d_out, int out_size){
    const float* x     = (const float*)d_in[0];
    const float* gam   = (const float*)d_in[1];
    const float* bet   = (const float*)d_in[2];
    const float* wqkv  = (const float*)d_in[3];
    const float* wout  = (const float*)d_in[4];
    const float* wgate = (const float*)d_in[5];
    const float* bgate = (const float*)d_in[6];
    const float* w1    = (const float*)d_in[7];
    const float* b1    = (const float*)d_in[8];
    const float* w2    = (const float*)d_in[9];
    const float* b2    = (const float*)d_in[10];
    float* out = (float*)d_out;

    cudaFuncSetAttribute(k_qkv,    cudaFuncAttributeMaxDynamicSharedMemorySize, GEMM_SMEM);
    cudaFuncSetAttribute(k_scores, cudaFuncAttributeMaxDynamicSharedMemorySize, GEMM_SMEM);
    cudaFuncSetAttribute(k_ctx,    cudaFuncAttributeMaxDynamicSharedMemorySize, GEMM_SMEM);
    cudaFuncSetAttribute(k_oproj,  cudaFuncAttributeMaxDynamicSharedMemorySize, GEMM_SMEM);
    cudaFuncSetAttribute(k_moe1,   cudaFuncAttributeMaxDynamicSharedMemorySize, GEMM_SMEM);
    cudaFuncSetAttribute(k_moe2,   cudaFuncAttributeMaxDynamicSharedMemorySize, GEMM_SMEM);

    k_zero<<<1,32>>>();
    k_ln1<<<dim3(Bn,64), 256>>>(x);
    k_ln2<<<Bn, 64>>>();
    k_ln<<<dim3(23,24,Bn), dim3(32,32)>>>(x, gam, bet);
    k_qkv<<<dim3((NTOK+127)/128, (3*Cn)/128), 256, GEMM_SMEM>>>(wqkv);
    k_scores<<<dim3(6,6,Bn*Hn), 256, GEMM_SMEM>>>();
    k_softmax<<<(Bn*Hn*Sn)/4, dim3(32,4)>>>();
    k_ctx<<<dim3(6,1,Bn*Hn), 256, GEMM_SMEM>>>();
    k_oproj<<<dim3((NTOK+127)/128, Cn/128), 256, GEMM_SMEM>>>(wout, x);
    k_gate<<<NTOK/8, dim3(32,8)>>>(wgate, bgate);
    k_denom<<<(Sn*En+255)/256, 256>>>();
    k_gs<<<(NTOK+255)/256, 256>>>();
    k_moe1<<<dim3((NTOK+127)/128, HIDn/128, En), 256, GEMM_SMEM>>>(w1, b1);
    k_moe2<<<dim3((NTOK+127)/128, Cn/128, En), 256, GEMM_SMEM>>>(w2, b2);
    k_final<<<dim3(23,24,Bn), dim3(32,32)>>>(out);
}

// round 4
// speedup vs baseline: 9.4401x; 1.7217x over previous
#include <cuda_runtime.h>
#include <cuda_fp16.h>
#include <math.h>
#include <stdint.h>

// Problem constants
#define Bn   16
#define Cn   768
#define Sn   729
#define Hn   8
#define Dn   96
#define En   3
#define HIDn 3072
#define NTOK (Bn*Sn)          // 11664
#define SP   736              // padded fp32 scores row stride
#define SPh  736              // padded fp16 probs row stride (16B-aligned: 736*2=1472)

// ---------------- scratch (device globals; no allocation allowed) -----------
__device__ __align__(256) float d_mu[Bn], d_rstd[Bn];
__device__ __align__(256) float d_part[Bn*64*2];
__device__ __align__(256) __half d_tok[(size_t)NTOK*Cn];
__device__ __align__(256) __half d_q[(size_t)Bn*Hn*Sn*Dn];
__device__ __align__(256) __half d_k[(size_t)Bn*Hn*Sn*Dn];
__device__ __align__(256) __half d_v[(size_t)Bn*Hn*Sn*Dn];
__device__ __align__(256) float  d_sc[(size_t)Bn*Hn*Sn*SP];   // fp32 scores
__device__ __align__(256) __half d_p[(size_t)Bn*Hn*Sn*SPh];   // fp16 probs
__device__ __align__(256) __half d_ctx[(size_t)NTOK*Cn];
__device__ __align__(256) float  d_x2[(size_t)NTOK*Cn];
__device__ __align__(256) __half d_x2h[(size_t)NTOK*Cn];
__device__ int   d_eid[NTOK];
__device__ float d_mg[NTOK];
__device__ float d_gs[NTOK];
__device__ float d_denom[Sn*En];
__device__ int   d_cnt[En];
__device__ int   d_list[En*NTOK];
__device__ __align__(256) __half d_hmid[(size_t)NTOK*HIDn];
__device__ __align__(256) float  d_moe[(size_t)NTOK*Cn];
// fp16 weight copies
__device__ __align__(256) __half d_wqkvh[(size_t)Cn*3*Cn];
__device__ __align__(256) __half d_wouth[(size_t)Cn*Cn];
__device__ __align__(256) __half d_w1h[(size_t)En*Cn*HIDn];
__device__ __align__(256) __half d_w2h[(size_t)En*HIDn*Cn];

// ---------------- primitives -------------------------------------------------
__device__ __forceinline__ void mma16816(float* c, const uint32_t* a, const uint32_t* b){
    asm volatile(
        "mma.sync.aligned.m16n8k16.row.col.f32.f16.f16.f32 "
        "{%0,%1,%2,%3}, {%4,%5,%6,%7}, {%8,%9}, {%0,%1,%2,%3};\n"
        : "+f"(c[0]), "+f"(c[1]), "+f"(c[2]), "+f"(c[3])
        : "r"(a[0]), "r"(a[1]), "r"(a[2]), "r"(a[3]), "r"(b[0]), "r"(b[1]));
}
__device__ __forceinline__ void ldsm4(uint32_t* r, uint32_t addr){
    asm volatile("ldmatrix.sync.aligned.m8n8.x4.shared.b16 {%0,%1,%2,%3}, [%4];"
        : "=r"(r[0]),"=r"(r[1]),"=r"(r[2]),"=r"(r[3]) : "r"(addr));
}
__device__ __forceinline__ void ldsm4t(uint32_t* r, uint32_t addr){
    asm volatile("ldmatrix.sync.aligned.m8n8.x4.trans.shared.b16 {%0,%1,%2,%3}, [%4];"
        : "=r"(r[0]),"=r"(r[1]),"=r"(r[2]),"=r"(r[3]) : "r"(addr));
}
__device__ __forceinline__ void cp16(uint32_t dst, const void* src, int sb){
    asm volatile("cp.async.cg.shared.global [%0], [%1], 16, %2;\n"
                 :: "r"(dst), "l"(src), "r"(sb));
}
__device__ __forceinline__ void cpcommit(){ asm volatile("cp.async.commit_group;\n"); }
template<int NW> __device__ __forceinline__ void cpwait(){
    asm volatile("cp.async.wait_group %0;\n" :: "n"(NW));
}

// ---------------- fp16 tensor-core GEMM core (cp.async + ldmatrix) ----------
// Block tile 128x128x64, 256 threads, warps 2x4, warp tile 64x32, fp32 accum.
// fA(m,k): &A[m][k], fp16, k-contiguous (16B-aligned at k%8==0).
// fB(k,n): BKF=false -> &B[k][n], n-contiguous (weights); staged [k][n] n-fast,
//          fragments via ldmatrix.trans.
//          BKF=true  -> &B^T[n][k], k-contiguous; staged [n][k] k-fast,
//          fragments via ldmatrix (same layout as A).
// SW128 xor swizzle on 16B chunks; conflict-free for both cp.async and ldmatrix.
template<bool BKF, class FA,class FB,class FC>
__device__ __forceinline__ void tgemm(int M,int N,int K, FA fA, FB fB, FC fC){
    constexpr int BM=128, BN=128, BK=64;
    extern __shared__ char sm_[];
    const uint32_t sA = (uint32_t)__cvta_generic_to_shared(sm_);
    const uint32_t sB = sA + 32768u;                 // A: 2 x 16KB
    const int tid = threadIdx.x;
    const int wid = tid >> 5, lane = tid & 31;
    const int wy  = wid >> 2, wx = wid & 3;
    const int gid = lane >> 2, tig = lane & 3;
    const int row0 = blockIdx.x * BM;
    const int col0 = blockIdx.y * BN;
    if (row0 >= M) return;

    float acc[4][4][4];
    #pragma unroll
    for (int i=0;i<4;i++)
        #pragma unroll
        for (int j=0;j<4;j++)
            #pragma unroll
            for (int r=0;r<4;r++) acc[i][j][r]=0.f;

    auto stage = [&](int buf, int k0){
        uint32_t aB = sA + (uint32_t)buf*16384u;
        #pragma unroll
        for (int i=0;i<4;i++){
            int idx = tid + i*256, m = idx >> 3, c = idx & 7;
            int gm = row0 + m, kg = k0 + c*8;
            const __half* src = fA(row0, 0); int sb = 0;
            if (gm < M && kg < K){
                src = fA(gm, kg);
                int rem = K - kg; sb = rem >= 8 ? 16 : rem*2;
            }
            cp16(aB + (uint32_t)(m*128 + ((c ^ (m&7))<<4)), src, sb);
        }
        uint32_t bB = sB + (uint32_t)buf*16384u;
        if (!BKF){
            #pragma unroll
            for (int i=0;i<4;i++){
                int idx = tid + i*256, k = idx >> 4, c = idx & 15;
                int kg = k0 + k, ng = col0 + c*8;
                const __half* src = fB(0, col0); int sb = 0;
                if (kg < K && ng < N){
                    src = fB(kg, ng);
                    int rem = N - ng; sb = rem >= 8 ? 16 : rem*2;
                }
                cp16(bB + (uint32_t)(k*256 + ((c ^ (k&7))<<4)), src, sb);
            }
        } else {
            #pragma unroll
            for (int i=0;i<4;i++){
                int idx = tid + i*256, n = idx >> 3, c = idx & 7;
                int gn = col0 + n, kg = k0 + c*8;
                const __half* src = fB(0, col0); int sb = 0;
                if (gn < N && kg < K){
                    src = fB(kg, gn);
                    int rem = K - kg; sb = rem >= 8 ? 16 : rem*2;
                }
                cp16(bB + (uint32_t)(n*128 + ((c ^ (n&7))<<4)), src, sb);
            }
        }
        cpcommit();
    };

    const int nk = (K + BK - 1) / BK;
    stage(0, 0);
    for (int t=0; t<nk; t++){
        const int buf = t & 1;
        if (t+1 < nk){ stage(buf^1, (t+1)*BK); cpwait<1>(); }
        else          { cpwait<0>(); }
        __syncthreads();
        const uint32_t aB = sA + (uint32_t)buf*16384u;
        const uint32_t bB = sB + (uint32_t)buf*16384u;
        const int j = lane >> 3, r = lane & 7;
        #pragma unroll
        for (int ks=0; ks<BK; ks+=16){
            uint32_t aF[4][4], bF[4][2];
            const int kc = (ks>>3) + (j>>1);
            #pragma unroll
            for (int mt=0; mt<4; mt++){
                int ml = wy*64 + mt*16 + (j&1)*8 + r;
                ldsm4(aF[mt], aB + (uint32_t)(ml*128 + ((kc ^ (ml&7))<<4)));
            }
            if (BKF){
                #pragma unroll
                for (int nt2=0; nt2<2; nt2++){
                    uint32_t d[4];
                    int nl = wx*32 + nt2*16 + (j&1)*8 + r;
                    ldsm4(d, bB + (uint32_t)(nl*128 + ((kc ^ (nl&7))<<4)));
                    bF[nt2*2+0][0]=d[0]; bF[nt2*2+0][1]=d[2];
                    bF[nt2*2+1][0]=d[1]; bF[nt2*2+1][1]=d[3];
                }
            } else {
                #pragma unroll
                for (int nt2=0; nt2<2; nt2++){
                    uint32_t d[4];
                    int kl = ks + (j&1)*8 + r;
                    int nc = wx*4 + nt2*2 + (j>>1);
                    ldsm4t(d, bB + (uint32_t)(kl*256 + ((nc ^ (kl&7))<<4)));
                    bF[nt2*2+0][0]=d[0]; bF[nt2*2+0][1]=d[1];
                    bF[nt2*2+1][0]=d[2]; bF[nt2*2+1][1]=d[3];
                }
            }
            #pragma unroll
            for (int mt=0; mt<4; mt++)
                #pragma unroll
                for (int nt=0; nt<4; nt++)
                    mma16816(acc[mt][nt], aF[mt], bF[nt]);
        }
        __syncthreads();
    }

    #pragma unroll
    for (int mt=0; mt<4; mt++){
        #pragma unroll
        for (int nt=0; nt<4; nt++){
            int mB = row0 + wy*64 + mt*16;
            int nB = col0 + wx*32 + nt*8;
            int r0 = mB + gid, r1 = mB + gid + 8;
            int c0 = nB + 2*tig, c1 = c0 + 1;
            if (r0 < M){
                if (c0 < N) fC(r0, c0, acc[mt][nt][0]);
                if (c1 < N) fC(r0, c1, acc[mt][nt][1]);
            }
            if (r1 < M){
                if (c0 < N) fC(r1, c0, acc[mt][nt][2]);
                if (c1 < N) fC(r1, c1, acc[mt][nt][3]);
            }
        }
    }
}

#define GEMM_SMEM 65536

// ---------------- kernels ----------------------------------------------------

__global__ void k_zero(){
    if (threadIdx.x < En) d_cnt[threadIdx.x] = 0;
}

// f32 -> f16 elementwise convert
__global__ void k_cvt(const float* __restrict__ src, __half* __restrict__ dst, int n){
    int i = blockIdx.x*256 + threadIdx.x;
    int stride = gridDim.x*256;
    for (; i < n; i += stride) dst[i] = __float2half(src[i]);
}

// LN stats pass 1
__global__ void k_ln1(const float* __restrict__ x){
    const int b = blockIdx.x, ch = blockIdx.y;
    const int CH = (Cn*Sn)/64;
    const float* xp = x + (size_t)b*Cn*Sn + (size_t)ch*CH;
    float s=0.f, s2=0.f;
    for (int i=threadIdx.x; i<CH; i+=256){ float v=xp[i]; s+=v; s2+=v*v; }
    __shared__ float sh[256], sh2[256];
    sh[threadIdx.x]=s; sh2[threadIdx.x]=s2;
    __syncthreads();
    for (int o=128; o>0; o>>=1){
        if (threadIdx.x<o){ sh[threadIdx.x]+=sh[threadIdx.x+o]; sh2[threadIdx.x]+=sh2[threadIdx.x+o]; }
        __syncthreads();
    }
    if (threadIdx.x==0){
        d_part[(b*64+ch)*2+0]=sh[0];
        d_part[(b*64+ch)*2+1]=sh2[0];
    }
}

// LN stats pass 2
__global__ void k_ln2(){
    const int b = blockIdx.x, t = threadIdx.x;   // 64 threads
    __shared__ float sh[64], sh2[64];
    sh[t]  = d_part[(b*64+t)*2+0];
    sh2[t] = d_part[(b*64+t)*2+1];
    __syncthreads();
    if (t < 32){ sh[t]+=sh[t+32]; sh2[t]+=sh2[t+32]; }
    __syncwarp();
    if (t < 32){
        float s=sh[t], s2=sh2[t];
        #pragma unroll
        for (int o=16;o>0;o>>=1){
            s  += __shfl_xor_sync(0xffffffffu, s,  o);
            s2 += __shfl_xor_sync(0xffffffffu, s2, o);
        }
        if (t==0){
            const float inv = 1.f/(float)(Cn*Sn);
            float mu = s*inv;
            float var = s2*inv - mu*mu;
            d_mu[b]=mu; d_rstd[b]=rsqrtf(var+1e-5f);
        }
    }
}

// xn = (x-mu)*rstd*gamma + beta, transposed [b,C,S] -> [b,S,C] fp16
__global__ void k_ln(const float* __restrict__ x, const float* __restrict__ g,
                     const float* __restrict__ be){
    __shared__ float tile[32][33];
    const int b = blockIdx.z;
    const int s0 = blockIdx.x*32, c0 = blockIdx.y*32;
    const float mu = d_mu[b], rs = d_rstd[b];
    {
        int s = s0+threadIdx.x, c = c0+threadIdx.y;
        if (s < Sn){
            float xv = x[((size_t)b*Cn+c)*Sn + s];
            tile[threadIdx.y][threadIdx.x] = (xv-mu)*rs*g[c*Sn+s] + be[c*Sn+s];
        }
    }
    __syncthreads();
    {
        int s = s0+threadIdx.y, c = c0+threadIdx.x;
        if (s < Sn)
            d_tok[((size_t)b*Sn+s)*Cn + c] = __float2half(tile[threadIdx.x][threadIdx.y]);
    }
}

// qkv = tok @ w_qkv ; scatter fp16 into q/k/v [b,h,s,d]
__global__ void __launch_bounds__(256,2) k_qkv(){
    tgemm<false>(NTOK, 3*Cn, Cn,
        [=] (int m,int k){ return d_tok + (size_t)m*Cn + k; },
        [=] (int k,int n){ return d_wqkvh + (size_t)k*3*Cn + n; },
        [=] (int m,int n,float v){
            int b=m/Sn, s=m%Sn;
            int which=n/Cn, r=n%Cn, h=r/Dn, dd=r%Dn;
            __half* dst = (which==0)? d_q : (which==1)? d_k : d_v;
            dst[(((size_t)b*Hn+h)*Sn+s)*Dn+dd] = __float2half(v);
        });
}

// scores[bh] = Q @ K^T (no 1/sqrt(d) scale), fp32 out
__global__ void __launch_bounds__(256,2) k_scores(){
    const int bh = blockIdx.z;
    const __half* Q  = d_q + (size_t)bh*Sn*Dn;
    const __half* Kp = d_k + (size_t)bh*Sn*Dn;
    float* Sc = d_sc + (size_t)bh*Sn*SP;
    tgemm<true>(Sn,Sn,Dn,
        [=] (int m,int k){ return Q + (size_t)m*Dn + k; },
        [=] (int k,int n){ return Kp + (size_t)n*Dn + k; },
        [=] (int m,int n,float v){ Sc[(size_t)m*SP+n]=v; });
}

// row softmax: fp32 in, fp16 out
__global__ void k_softmax(){
    const int row = blockIdx.x*4 + threadIdx.y;
    if (row >= Bn*Hn*Sn) return;
    const float* p = d_sc + (size_t)row*SP;
    __half* o = d_p + (size_t)row*SPh;
    const int lane = threadIdx.x;
    float mx = -1e30f;
    for (int i=lane;i<Sn;i+=32) mx = fmaxf(mx, p[i]);
    #pragma unroll
    for (int of=16;of>0;of>>=1) mx = fmaxf(mx, __shfl_xor_sync(0xffffffffu, mx, of));
    float sum = 0.f;
    for (int i=lane;i<Sn;i+=32) sum += expf(p[i]-mx);
    #pragma unroll
    for (int of=16;of>0;of>>=1) sum += __shfl_xor_sync(0xffffffffu, sum, of);
    const float inv = 1.f/sum;
    for (int i=lane;i<Sn;i+=32) o[i] = __float2half(expf(p[i]-mx)*inv);
}

// ctx[bh] = P @ V, fp16 out scattered to [b,s, h*96+d]
__global__ void __launch_bounds__(256,2) k_ctx(){
    const int bh = blockIdx.z;
    const int b = bh/Hn, h = bh%Hn;
    const __half* P = d_p + (size_t)bh*Sn*SPh;
    const __half* V = d_v + (size_t)bh*Sn*Dn;
    tgemm<false>(Sn,Dn,Sn,
        [=] (int m,int k){ return P + (size_t)m*SPh + k; },
        [=] (int k,int n){ return V + (size_t)k*Dn + n; },
        [=] (int m,int n,float v){
            d_ctx[((size_t)b*Sn+m)*Cn + h*Dn + n] = __float2half(v);
        });
}

// x2 = ctx @ w_out + x; fp32 + fp16 copies
__global__ void __launch_bounds__(256,2) k_oproj(const float* __restrict__ x){
    tgemm<false>(NTOK,Cn,Cn,
        [=] (int m,int k){ return d_ctx + (size_t)m*Cn + k; },
        [=] (int k,int n){ return d_wouth + (size_t)k*Cn + n; },
        [=] (int m,int n,float v){
            int b=m/Sn, s=m%Sn;
            float r = v + x[((size_t)b*Cn+n)*Sn+s];
            d_x2[(size_t)m*Cn+n]  = r;
            d_x2h[(size_t)m*Cn+n] = __float2half(r);
        });
}

// gate: logits, softmax3, argmax, mg
__global__ void k_gate(const float* __restrict__ wg, const float* __restrict__ bg){
    const int t = blockIdx.x*8 + threadIdx.y;
    if (t >= NTOK) return;
    const int lane = threadIdx.x;
    const float* xr = d_x2 + (size_t)t*Cn;
    float a0=0.f,a1=0.f,a2=0.f;
    for (int c=lane;c<Cn;c+=32){
        float v = xr[c];
        a0 = fmaf(v, wg[c*3+0], a0);
        a1 = fmaf(v, wg[c*3+1], a1);
        a2 = fmaf(v, wg[c*3+2], a2);
    }
    #pragma unroll
    for (int o=16;o>0;o>>=1){
        a0 += __shfl_xor_sync(0xffffffffu,a0,o);
        a1 += __shfl_xor_sync(0xffffffffu,a1,o);
        a2 += __shfl_xor_sync(0xffffffffu,a2,o);
    }
    if (lane==0){
        a0+=bg[0]; a1+=bg[1]; a2+=bg[2];
        int am=0; float m=a0;
        if (a1>m){m=a1;am=1;}
        if (a2>m){m=a2;am=2;}
        float e0=expf(a0-m), e1=expf(a1-m), e2=expf(a2-m);
        float sum=e0+e1+e2;
        float pm = ((am==0)?e0:(am==1)?e1:e2)/sum;
        d_eid[t]=am; d_mg[t]=pm;
    }
}

// denom[s,e] = sum_b mg (deterministic order)
__global__ void k_denom(){
    const int i = blockIdx.x*256 + threadIdx.x;
    if (i >= Sn*En) return;
    const int s = i/En, e = i%En;
    float acc = 0.f;
    #pragma unroll
    for (int b=0;b<Bn;b++){
        int t = b*Sn+s;
        if (d_eid[t]==e) acc += d_mg[t];
    }
    d_denom[i] = acc;
}

// gate score + expert bucket lists
__global__ void k_gs(){
    const int t = blockIdx.x*256 + threadIdx.x;
    if (t >= NTOK) return;
    const int e = d_eid[t], s = t % Sn;
    d_gs[t] = d_mg[t] / (d_denom[s*En+e] + 1e-6f) * (float)Bn;
    int pos = atomicAdd(&d_cnt[e], 1);
    d_list[e*NTOK + pos] = t;
}

// expert FFN layer 1 + exact GELU (gathered rows), fp16 out
__global__ void __launch_bounds__(256,2) k_moe1(const float* __restrict__ b1){
    const int e = blockIdx.z;
    const int cnt = d_cnt[e];
    const int* lst = d_list + e*NTOK;
    const __half* W = d_w1h + (size_t)e*Cn*HIDn;
    tgemm<false>(cnt,HIDn,Cn,
        [=] (int m,int k){ return d_x2h + (size_t)lst[m]*Cn + k; },
        [=] (int k,int n){ return W + (size_t)k*HIDn + n; },
        [=] (int m,int n,float v){
            float xg = v + b1[e*HIDn+n];
            float gl = 0.5f*xg*(1.f + erff(xg*0.70710678118654752f));
            d_hmid[(size_t)lst[m]*HIDn+n] = __float2half(gl);
        });
}

// expert FFN layer 2, scaled by gate score
__global__ void __launch_bounds__(256,2) k_moe2(const float* __restrict__ b2){
    const int e = blockIdx.z;
    const int cnt = d_cnt[e];
    const int* lst = d_list + e*NTOK;
    const __half* W = d_w2h + (size_t)e*HIDn*Cn;
    tgemm<false>(cnt,Cn,HIDn,
        [=] (int m,int k){ return d_hmid + (size_t)lst[m]*HIDn + k; },
        [=] (int k,int n){ return W + (size_t)k*Cn + n; },
        [=] (int m,int n,float v){
            int t = lst[m];
            d_moe[(size_t)t*Cn+n] = (v + b2[e*Cn+n]) * d_gs[t];
        });
}

// out[b,c,s] = x2[b,s,c] + moe[b,s,c]
__global__ void k_final(float* __restrict__ out){
    __shared__ float tile[32][33];
    const int b = blockIdx.z;
    const int s0 = blockIdx.x*32, c0 = blockIdx.y*32;
    {
        int s = s0+threadIdx.y, c = c0+threadIdx.x;
        if (s < Sn){
            size_t idx = ((size_t)b*Sn+s)*Cn + c;
            tile[threadIdx.y][threadIdx.x] = d_x2[idx] + d_moe[idx];
        }
    }
    __syncthreads();
    {
        int s = s0+threadIdx.x, c = c0+threadIdx.y;
        if (s < Sn)
            out[((size_t)b*Cn+c)*Sn + s] = tile[threadIdx.x][threadIdx.y];
    }
}

// ---------------- launch ------------------------------------------------------
extern "C" void kernel_launch(void* const* d_in, const int* in_sizes, int n_in,
                              void* d_out, int out_size){
    const float* x     = (const float*)d_in[0];
    const float* gam   = (const float*)d_in[1];
    const float* bet   = (const float*)d_in[2];
    const float* wqkv  = (const float*)d_in[3];
    const float* wout  = (const float*)d_in[4];
    const float* wgate = (const float*)d_in[5];
    const float* bgate = (const float*)d_in[6];
    const float* w1    = (const float*)d_in[7];
    const float* b1    = (const float*)d_in[8];
    const float* w2    = (const float*)d_in[9];
    const float* b2    = (const float*)d_in[10];
    float* out = (float*)d_out;

    cudaFuncSetAttribute(k_qkv,    cudaFuncAttributeMaxDynamicSharedMemorySize, GEMM_SMEM);
    cudaFuncSetAttribute(k_scores, cudaFuncAttributeMaxDynamicSharedMemorySize, GEMM_SMEM);
    cudaFuncSetAttribute(k_ctx,    cudaFuncAttributeMaxDynamicSharedMemorySize, GEMM_SMEM);
    cudaFuncSetAttribute(k_oproj,  cudaFuncAttributeMaxDynamicSharedMemorySize, GEMM_SMEM);
    cudaFuncSetAttribute(k_moe1,   cudaFuncAttributeMaxDynamicSharedMemorySize, GEMM_SMEM);
    cudaFuncSetAttribute(k_moe2,   cudaFuncAttributeMaxDynamicSharedMemorySize, GEMM_SMEM);

    // weight fp16 conversion
    __half* wqkvh_p; cudaGetSymbolAddress((void**)&wqkvh_p, d_wqkvh);
    __half* wouth_p; cudaGetSymbolAddress((void**)&wouth_p, d_wouth);
    __half* w1h_p;   cudaGetSymbolAddress((void**)&w1h_p,   d_w1h);
    __half* w2h_p;   cudaGetSymbolAddress((void**)&w2h_p,   d_w2h);
    k_cvt<<<1024,256>>>(wqkv, wqkvh_p, Cn*3*Cn);
    k_cvt<<<1024,256>>>(wout, wouth_p, Cn*Cn);
    k_cvt<<<2048,256>>>(w1,   w1h_p,   En*Cn*HIDn);
    k_cvt<<<2048,256>>>(w2,   w2h_p,   En*HIDn*Cn);

    k_zero<<<1,32>>>();
    k_ln1<<<dim3(Bn,64), 256>>>(x);
    k_ln2<<<Bn, 64>>>();
    k_ln<<<dim3(23,24,Bn), dim3(32,32)>>>(x, gam, bet);
    k_qkv<<<dim3((NTOK+127)/128, (3*Cn)/128), 256, GEMM_SMEM>>>();
    k_scores<<<dim3(6,6,Bn*Hn), 256, GEMM_SMEM>>>();
    k_softmax<<<(Bn*Hn*Sn)/4, dim3(32,4)>>>();
    k_ctx<<<dim3(6,1,Bn*Hn), 256, GEMM_SMEM>>>();
    k_oproj<<<dim3((NTOK+127)/128, Cn/128), 256, GEMM_SMEM>>>(x);
    k_gate<<<NTOK/8, dim3(32,8)>>>(wgate, bgate);
    k_denom<<<(Sn*En+255)/256, 256>>>();
    k_gs<<<(NTOK+255)/256, 256>>>();
    k_moe1<<<dim3((NTOK+127)/128, HIDn/128, En), 256, GEMM_SMEM>>>(b1);
    k_moe2<<<dim3((NTOK+127)/128, Cn/128, En), 256, GEMM_SMEM>>>(b2);
    k_final<<<dim3(23,24,Bn), dim3(32,32)>>>(out);
}

// round 5
// speedup vs baseline: 10.9421x; 1.1591x over previous
#include <cuda_runtime.h>
#include <cuda_fp16.h>
#include <math.h>
#include <stdint.h>

// Problem constants
#define Bn   16
#define Cn   768
#define Sn   729
#define Hn   8
#define Dn   96
#define En   3
#define HIDn 3072
#define NTOK (Bn*Sn)          // 11664

// ---------------- scratch (device globals; no allocation allowed) -----------
__device__ __align__(256) float d_mu[Bn], d_rstd[Bn];
__device__ __align__(256) float d_part[Bn*64*2];
__device__ __align__(256) __half d_tok[(size_t)NTOK*Cn];
__device__ __align__(256) __half d_q[(size_t)Bn*Hn*Sn*Dn];
__device__ __align__(256) __half d_k[(size_t)Bn*Hn*Sn*Dn];
__device__ __align__(256) __half d_v[(size_t)Bn*Hn*Sn*Dn];
__device__ __align__(256) __half d_ctx[(size_t)NTOK*Cn];
__device__ __align__(256) float  d_x2[(size_t)NTOK*Cn];
__device__ __align__(256) __half d_x2h[(size_t)NTOK*Cn];
__device__ int   d_eid[NTOK];
__device__ float d_mg[NTOK];
__device__ float d_gs[NTOK];
__device__ float d_denom[Sn*En];
__device__ int   d_cnt[En];
__device__ int   d_list[En*NTOK];
__device__ __align__(256) __half d_hmid[(size_t)NTOK*HIDn];
__device__ __align__(256) float  d_moe[(size_t)NTOK*Cn];
// fp16 weight copies
__device__ __align__(256) __half d_wqkvh[(size_t)Cn*3*Cn];
__device__ __align__(256) __half d_wouth[(size_t)Cn*Cn];
__device__ __align__(256) __half d_w1h[(size_t)En*Cn*HIDn];
__device__ __align__(256) __half d_w2h[(size_t)En*HIDn*Cn];

// ---------------- primitives -------------------------------------------------
__device__ __forceinline__ void mma16816(float* c, const uint32_t* a, const uint32_t* b){
    asm volatile(
        "mma.sync.aligned.m16n8k16.row.col.f32.f16.f16.f32 "
        "{%0,%1,%2,%3}, {%4,%5,%6,%7}, {%8,%9}, {%0,%1,%2,%3};\n"
        : "+f"(c[0]), "+f"(c[1]), "+f"(c[2]), "+f"(c[3])
        : "r"(a[0]), "r"(a[1]), "r"(a[2]), "r"(a[3]), "r"(b[0]), "r"(b[1]));
}
__device__ __forceinline__ void ldsm4(uint32_t* r, uint32_t addr){
    asm volatile("ldmatrix.sync.aligned.m8n8.x4.shared.b16 {%0,%1,%2,%3}, [%4];"
        : "=r"(r[0]),"=r"(r[1]),"=r"(r[2]),"=r"(r[3]) : "r"(addr));
}
__device__ __forceinline__ void ldsm4t(uint32_t* r, uint32_t addr){
    asm volatile("ldmatrix.sync.aligned.m8n8.x4.trans.shared.b16 {%0,%1,%2,%3}, [%4];"
        : "=r"(r[0]),"=r"(r[1]),"=r"(r[2]),"=r"(r[3]) : "r"(addr));
}
__device__ __forceinline__ void cp16(uint32_t dst, const void* src, int sb){
    asm volatile("cp.async.cg.shared.global [%0], [%1], 16, %2;\n"
                 :: "r"(dst), "l"(src), "r"(sb));
}
__device__ __forceinline__ void cpcommit(){ asm volatile("cp.async.commit_group;\n"); }
template<int NW> __device__ __forceinline__ void cpwait(){
    asm volatile("cp.async.wait_group %0;\n" :: "n"(NW));
}
__device__ __forceinline__ uint32_t h2u(float a, float b){
    __half2 h = __floats2half2_rn(a, b);
    return *(uint32_t*)&h;
}

// ---------------- fp16 tensor-core GEMM core (3-stage cp.async) -------------
// Block tile 128x128x64, 256 threads, warps 2x4, warp tile 64x32, fp32 accum.
template<bool BKF, class FA,class FB,class FC>
__device__ __forceinline__ void tgemm(int M,int N,int K, FA fA, FB fB, FC fC){
    constexpr int BM=128, BN=128, BK=64;
    extern __shared__ char sm_[];
    const uint32_t sA = (uint32_t)__cvta_generic_to_shared(sm_);
    const uint32_t sB = sA + 49152u;                 // A: 3 x 16KB
    const int tid = threadIdx.x;
    const int wid = tid >> 5, lane = tid & 31;
    const int wy  = wid >> 2, wx = wid & 3;
    const int gid = lane >> 2, tig = lane & 3;
    const int row0 = blockIdx.x * BM;
    const int col0 = blockIdx.y * BN;
    if (row0 >= M) return;

    float acc[4][4][4];
    #pragma unroll
    for (int i=0;i<4;i++)
        #pragma unroll
        for (int j=0;j<4;j++)
            #pragma unroll
            for (int r=0;r<4;r++) acc[i][j][r]=0.f;

    auto stage = [&](int buf, int k0){
        uint32_t aB = sA + (uint32_t)buf*16384u;
        #pragma unroll
        for (int i=0;i<4;i++){
            int idx = tid + i*256, m = idx >> 3, c = idx & 7;
            int gm = row0 + m, kg = k0 + c*8;
            const __half* src = fA(row0, 0); int sb = 0;
            if (gm < M && kg < K){
                src = fA(gm, kg);
                int rem = K - kg; sb = rem >= 8 ? 16 : rem*2;
            }
            cp16(aB + (uint32_t)(m*128 + ((c ^ (m&7))<<4)), src, sb);
        }
        uint32_t bB = sB + (uint32_t)buf*16384u;
        if (!BKF){
            #pragma unroll
            for (int i=0;i<4;i++){
                int idx = tid + i*256, k = idx >> 4, c = idx & 15;
                int kg = k0 + k, ng = col0 + c*8;
                const __half* src = fB(0, col0); int sb = 0;
                if (kg < K && ng < N){
                    src = fB(kg, ng);
                    int rem = N - ng; sb = rem >= 8 ? 16 : rem*2;
                }
                cp16(bB + (uint32_t)(k*256 + ((c ^ (k&7))<<4)), src, sb);
            }
        } else {
            #pragma unroll
            for (int i=0;i<4;i++){
                int idx = tid + i*256, n = idx >> 3, c = idx & 7;
                int gn = col0 + n, kg = k0 + c*8;
                const __half* src = fB(0, col0); int sb = 0;
                if (gn < N && kg < K){
                    src = fB(kg, gn);
                    int rem = K - kg; sb = rem >= 8 ? 16 : rem*2;
                }
                cp16(bB + (uint32_t)(n*128 + ((c ^ (n&7))<<4)), src, sb);
            }
        }
        cpcommit();
    };

    const int nk = (K + BK - 1) / BK;
    stage(0, 0);
    if (nk > 1) stage(1, BK);
    for (int t=0; t<nk; t++){
        const int buf = t % 3;
        if (t+2 < nk) stage((t+2)%3, (t+2)*BK);
        const int rem = nk-1-t;
        if (rem >= 2)      cpwait<2>();
        else if (rem == 1) cpwait<1>();
        else               cpwait<0>();
        __syncthreads();
        const uint32_t aB = sA + (uint32_t)buf*16384u;
        const uint32_t bB = sB + (uint32_t)buf*16384u;
        const int j = lane >> 3, r = lane & 7;
        #pragma unroll
        for (int ks=0; ks<BK; ks+=16){
            uint32_t aF[4][4], bF[4][2];
            const int kc = (ks>>3) + (j>>1);
            #pragma unroll
            for (int mt=0; mt<4; mt++){
                int ml = wy*64 + mt*16 + (j&1)*8 + r;
                ldsm4(aF[mt], aB + (uint32_t)(ml*128 + ((kc ^ (ml&7))<<4)));
            }
            if (BKF){
                #pragma unroll
                for (int nt2=0; nt2<2; nt2++){
                    uint32_t d[4];
                    int nl = wx*32 + nt2*16 + (j&1)*8 + r;
                    ldsm4(d, bB + (uint32_t)(nl*128 + ((kc ^ (nl&7))<<4)));
                    bF[nt2*2+0][0]=d[0]; bF[nt2*2+0][1]=d[2];
                    bF[nt2*2+1][0]=d[1]; bF[nt2*2+1][1]=d[3];
                }
            } else {
                #pragma unroll
                for (int nt2=0; nt2<2; nt2++){
                    uint32_t d[4];
                    int kl = ks + (j&1)*8 + r;
                    int nc = wx*4 + nt2*2 + (j>>1);
                    ldsm4t(d, bB + (uint32_t)(kl*256 + ((nc ^ (kl&7))<<4)));
                    bF[nt2*2+0][0]=d[0]; bF[nt2*2+0][1]=d[1];
                    bF[nt2*2+1][0]=d[2]; bF[nt2*2+1][1]=d[3];
                }
            }
            #pragma unroll
            for (int mt=0; mt<4; mt++)
                #pragma unroll
                for (int nt=0; nt<4; nt++)
                    mma16816(acc[mt][nt], aF[mt], bF[nt]);
        }
        __syncthreads();
    }

    #pragma unroll
    for (int mt=0; mt<4; mt++){
        #pragma unroll
        for (int nt=0; nt<4; nt++){
            int mB = row0 + wy*64 + mt*16;
            int nB = col0 + wx*32 + nt*8;
            int r0 = mB + gid, r1 = mB + gid + 8;
            int c0 = nB + 2*tig, c1 = c0 + 1;
            if (r0 < M){
                if (c0 < N) fC(r0, c0, acc[mt][nt][0]);
                if (c1 < N) fC(r0, c1, acc[mt][nt][1]);
            }
            if (r1 < M){
                if (c0 < N) fC(r1, c0, acc[mt][nt][2]);
                if (c1 < N) fC(r1, c1, acc[mt][nt][3]);
            }
        }
    }
}

#define GEMM_SMEM 98304

// ---------------- fused flash attention --------------------------------------
// grid (6, Bn*Hn), 256 threads (8 warps, warp w owns q rows 16w..16w+15).
// SMEM rows padded to 104 halfs (208B) -> conflict-free ldmatrix (stride 52
// words: banks {0,20,8,28,16,4,24,12} per 8-row phase).
#define ATT_TILE_B 26624          // 128*104*2 bytes
#define ATT_SMEM  (5*ATT_TILE_B)  // Q + 2xK + 2xV = 133120

__global__ void __launch_bounds__(256,1) k_attn(){
    extern __shared__ char sm_[];
    const uint32_t base = (uint32_t)__cvta_generic_to_shared(sm_);
    const uint32_t qB = base;
    const int tid = threadIdx.x;
    const int w = tid >> 5, lane = tid & 31;
    const int gid = lane >> 2, tig = lane & 3;
    const int j = lane >> 3, r = lane & 7;
    const int bh = blockIdx.y;
    const int b = bh >> 3, h = bh & 7;
    const int q0 = blockIdx.x * 128;
    const __half* Qg = d_q + (size_t)bh*Sn*Dn;
    const __half* Kg = d_k + (size_t)bh*Sn*Dn;
    const __half* Vg = d_v + (size_t)bh*Sn*Dn;

    // stage Q (128 rows x 12 16B-chunks)
    #pragma unroll
    for (int i=0;i<6;i++){
        int idx = tid + i*256, m = idx/12, c = idx%12;
        int gm = q0 + m;
        const __half* src = Qg; int sb = 0;
        if (gm < Sn){ src = Qg + (size_t)gm*Dn + c*8; sb = 16; }
        cp16(qB + (uint32_t)(m*208 + c*16), src, sb);
    }
    auto stKV = [&](int buf, int k0){
        uint32_t kBs = base + (uint32_t)(1+buf)*ATT_TILE_B;
        uint32_t vBs = base + (uint32_t)(3+buf)*ATT_TILE_B;
        #pragma unroll
        for (int i=0;i<6;i++){
            int idx = tid + i*256, m = idx/12, c = idx%12;
            int gk = k0 + m;
            const __half* sk = Kg; const __half* sv = Vg; int sb = 0;
            if (gk < Sn){
                sk = Kg + (size_t)gk*Dn + c*8;
                sv = Vg + (size_t)gk*Dn + c*8;
                sb = 16;
            }
            cp16(kBs + (uint32_t)(m*208 + c*16), sk, sb);
            cp16(vBs + (uint32_t)(m*208 + c*16), sv, sb);
        }
    };
    stKV(0, 0); cpcommit();
    stKV(1, 128); cpcommit();

    float oAcc[12][4];
    #pragma unroll
    for (int i=0;i<12;i++){ oAcc[i][0]=0.f; oAcc[i][1]=0.f; oAcc[i][2]=0.f; oAcc[i][3]=0.f; }
    float mPrev0 = -1e30f, mPrev1 = -1e30f;
    float l0 = 0.f, l1 = 0.f;

    const int nkt = 6;   // ceil(729/128)
    for (int it=0; it<nkt; it++){
        const int buf = it & 1;
        if (it+1 < nkt) cpwait<1>(); else cpwait<0>();
        __syncthreads();
        const uint32_t kB = base + (uint32_t)(1+buf)*ATT_TILE_B;
        const uint32_t vB = base + (uint32_t)(3+buf)*ATT_TILE_B;

        // ---- S = Q @ K^T (warp: 16 q-rows x 128 keys) ----
        float sAcc[16][4];
        #pragma unroll
        for (int i=0;i<16;i++){ sAcc[i][0]=0.f; sAcc[i][1]=0.f; sAcc[i][2]=0.f; sAcc[i][3]=0.f; }
        #pragma unroll
        for (int t=0;t<6;t++){
            uint32_t aF[4];
            const int kc = 2*t + (j>>1);
            const int ml = w*16 + (j&1)*8 + r;
            ldsm4(aF, qB + (uint32_t)(ml*208 + kc*16));
            #pragma unroll
            for (int nt2=0; nt2<8; nt2++){
                uint32_t d4[4], b0[2], b1[2];
                int nl = nt2*16 + (j&1)*8 + r;
                ldsm4(d4, kB + (uint32_t)(nl*208 + kc*16));
                b0[0]=d4[0]; b0[1]=d4[2];
                b1[0]=d4[1]; b1[1]=d4[3];
                mma16816(sAcc[nt2*2],   aF, b0);
                mma16816(sAcc[nt2*2+1], aF, b1);
            }
        }

        // ---- online softmax ----
        const int kRem = Sn - it*128;
        if (kRem < 128){
            #pragma unroll
            for (int nt=0; nt<16; nt++){
                int c0 = nt*8 + 2*tig;
                if (c0   >= kRem){ sAcc[nt][0] = -1e30f; sAcc[nt][2] = -1e30f; }
                if (c0+1 >= kRem){ sAcc[nt][1] = -1e30f; sAcc[nt][3] = -1e30f; }
            }
        }
        float mN0 = -1e30f, mN1 = -1e30f;
        #pragma unroll
        for (int nt=0; nt<16; nt++){
            mN0 = fmaxf(mN0, fmaxf(sAcc[nt][0], sAcc[nt][1]));
            mN1 = fmaxf(mN1, fmaxf(sAcc[nt][2], sAcc[nt][3]));
        }
        mN0 = fmaxf(mN0, __shfl_xor_sync(0xffffffffu, mN0, 1));
        mN0 = fmaxf(mN0, __shfl_xor_sync(0xffffffffu, mN0, 2));
        mN1 = fmaxf(mN1, __shfl_xor_sync(0xffffffffu, mN1, 1));
        mN1 = fmaxf(mN1, __shfl_xor_sync(0xffffffffu, mN1, 2));
        const float mT0 = fmaxf(mPrev0, mN0);
        const float mT1 = fmaxf(mPrev1, mN1);
        const float sc0 = __expf(mPrev0 - mT0);
        const float sc1 = __expf(mPrev1 - mT1);
        mPrev0 = mT0; mPrev1 = mT1;

        float rs0 = 0.f, rs1 = 0.f;
        uint32_t pF[8][4];
        #pragma unroll
        for (int t=0;t<8;t++){
            float e00 = __expf(sAcc[2*t][0]  - mT0), e01 = __expf(sAcc[2*t][1]  - mT0);
            float e10 = __expf(sAcc[2*t][2]  - mT1), e11 = __expf(sAcc[2*t][3]  - mT1);
            float f00 = __expf(sAcc[2*t+1][0]- mT0), f01 = __expf(sAcc[2*t+1][1]- mT0);
            float f10 = __expf(sAcc[2*t+1][2]- mT1), f11 = __expf(sAcc[2*t+1][3]- mT1);
            rs0 += e00+e01+f00+f01;
            rs1 += e10+e11+f10+f11;
            pF[t][0] = h2u(e00,e01); pF[t][1] = h2u(e10,e11);
            pF[t][2] = h2u(f00,f01); pF[t][3] = h2u(f10,f11);
        }
        rs0 += __shfl_xor_sync(0xffffffffu, rs0, 1);
        rs0 += __shfl_xor_sync(0xffffffffu, rs0, 2);
        rs1 += __shfl_xor_sync(0xffffffffu, rs1, 1);
        rs1 += __shfl_xor_sync(0xffffffffu, rs1, 2);
        l0 = l0*sc0 + rs0;
        l1 = l1*sc1 + rs1;
        #pragma unroll
        for (int i=0;i<12;i++){
            oAcc[i][0]*=sc0; oAcc[i][1]*=sc0;
            oAcc[i][2]*=sc1; oAcc[i][3]*=sc1;
        }

        // ---- O += P @ V ----
        #pragma unroll
        for (int t=0;t<8;t++){
            const int kl = t*16 + (j&1)*8 + r;
            #pragma unroll
            for (int nt2=0; nt2<6; nt2++){
                uint32_t d4[4], b0[2], b1[2];
                int nc = nt2*2 + (j>>1);
                ldsm4t(d4, vB + (uint32_t)(kl*208 + nc*16));
                b0[0]=d4[0]; b0[1]=d4[1];
                b1[0]=d4[2]; b1[1]=d4[3];
                mma16816(oAcc[nt2*2],   pF[t], b0);
                mma16816(oAcc[nt2*2+1], pF[t], b1);
            }
        }
        __syncthreads();
        if (it+2 < nkt){ stKV(buf, (it+2)*128); cpcommit(); }
    }

    // epilogue: O/l -> d_ctx [b,s, h*96+d] fp16
    const float inv0 = 1.f/l0, inv1 = 1.f/l1;
    const int row0g = q0 + w*16 + gid;
    const int row1g = row0g + 8;
    #pragma unroll
    for (int nt=0; nt<12; nt++){
        int col = h*Dn + nt*8 + 2*tig;
        if (row0g < Sn){
            __half2 hv = __floats2half2_rn(oAcc[nt][0]*inv0, oAcc[nt][1]*inv0);
            *(__half2*)&d_ctx[((size_t)b*Sn+row0g)*Cn + col] = hv;
        }
        if (row1g < Sn){
            __half2 hv = __floats2half2_rn(oAcc[nt][2]*inv1, oAcc[nt][3]*inv1);
            *(__half2*)&d_ctx[((size_t)b*Sn+row1g)*Cn + col] = hv;
        }
    }
}

// ---------------- kernels ----------------------------------------------------

__global__ void k_zero(){
    if (threadIdx.x < En) d_cnt[threadIdx.x] = 0;
}

// f32 -> f16 vectorized convert (n % 4 == 0)
__global__ void k_cvt(const float4* __restrict__ src, __half2* __restrict__ dst, int n4){
    int i = blockIdx.x*256 + threadIdx.x;
    int stride = gridDim.x*256;
    for (; i < n4; i += stride){
        float4 v = src[i];
        dst[2*i]   = __floats2half2_rn(v.x, v.y);
        dst[2*i+1] = __floats2half2_rn(v.z, v.w);
    }
}

// LN stats pass 1
__global__ void k_ln1(const float* __restrict__ x){
    const int b = blockIdx.x, ch = blockIdx.y;
    const int CH = (Cn*Sn)/64;
    const float* xp = x + (size_t)b*Cn*Sn + (size_t)ch*CH;
    float s=0.f, s2=0.f;
    for (int i=threadIdx.x; i<CH; i+=256){ float v=xp[i]; s+=v; s2+=v*v; }
    __shared__ float sh[256], sh2[256];
    sh[threadIdx.x]=s; sh2[threadIdx.x]=s2;
    __syncthreads();
    for (int o=128; o>0; o>>=1){
        if (threadIdx.x<o){ sh[threadIdx.x]+=sh[threadIdx.x+o]; sh2[threadIdx.x]+=sh2[threadIdx.x+o]; }
        __syncthreads();
    }
    if (threadIdx.x==0){
        d_part[(b*64+ch)*2+0]=sh[0];
        d_part[(b*64+ch)*2+1]=sh2[0];
    }
}

// LN stats pass 2
__global__ void k_ln2(){
    const int b = blockIdx.x, t = threadIdx.x;   // 64 threads
    __shared__ float sh[64], sh2[64];
    sh[t]  = d_part[(b*64+t)*2+0];
    sh2[t] = d_part[(b*64+t)*2+1];
    __syncthreads();
    if (t < 32){ sh[t]+=sh[t+32]; sh2[t]+=sh2[t+32]; }
    __syncwarp();
    if (t < 32){
        float s=sh[t], s2=sh2[t];
        #pragma unroll
        for (int o=16;o>0;o>>=1){
            s  += __shfl_xor_sync(0xffffffffu, s,  o);
            s2 += __shfl_xor_sync(0xffffffffu, s2, o);
        }
        if (t==0){
            const float inv = 1.f/(float)(Cn*Sn);
            float mu = s*inv;
            float var = s2*inv - mu*mu;
            d_mu[b]=mu; d_rstd[b]=rsqrtf(var+1e-5f);
        }
    }
}

// xn = (x-mu)*rstd*gamma + beta, transposed [b,C,S] -> [b,S,C] fp16
__global__ void k_ln(const float* __restrict__ x, const float* __restrict__ g,
                     const float* __restrict__ be){
    __shared__ float tile[32][33];
    const int b = blockIdx.z;
    const int s0 = blockIdx.x*32, c0 = blockIdx.y*32;
    const float mu = d_mu[b], rs = d_rstd[b];
    {
        int s = s0+threadIdx.x, c = c0+threadIdx.y;
        if (s < Sn){
            float xv = x[((size_t)b*Cn+c)*Sn + s];
            tile[threadIdx.y][threadIdx.x] = (xv-mu)*rs*g[c*Sn+s] + be[c*Sn+s];
        }
    }
    __syncthreads();
    {
        int s = s0+threadIdx.y, c = c0+threadIdx.x;
        if (s < Sn)
            d_tok[((size_t)b*Sn+s)*Cn + c] = __float2half(tile[threadIdx.x][threadIdx.y]);
    }
}

// qkv = tok @ w_qkv ; scatter fp16 into q/k/v [b,h,s,d]
__global__ void __launch_bounds__(256,2) k_qkv(){
    tgemm<false>(NTOK, 3*Cn, Cn,
        [=] (int m,int k){ return d_tok + (size_t)m*Cn + k; },
        [=] (int k,int n){ return d_wqkvh + (size_t)k*3*Cn + n; },
        [=] (int m,int n,float v){
            int b=m/Sn, s=m%Sn;
            int which=n/Cn, r=n%Cn, h=r/Dn, dd=r%Dn;
            __half* dst = (which==0)? d_q : (which==1)? d_k : d_v;
            dst[(((size_t)b*Hn+h)*Sn+s)*Dn+dd] = __float2half(v);
        });
}

// x2 = ctx @ w_out + x; fp32 + fp16 copies
__global__ void __launch_bounds__(256,2) k_oproj(const float* __restrict__ x){
    tgemm<false>(NTOK,Cn,Cn,
        [=] (int m,int k){ return d_ctx + (size_t)m*Cn + k; },
        [=] (int k,int n){ return d_wouth + (size_t)k*Cn + n; },
        [=] (int m,int n,float v){
            int b=m/Sn, s=m%Sn;
            float r = v + x[((size_t)b*Cn+n)*Sn+s];
            d_x2[(size_t)m*Cn+n]  = r;
            d_x2h[(size_t)m*Cn+n] = __float2half(r);
        });
}

// gate: logits, softmax3, argmax, mg
__global__ void k_gate(const float* __restrict__ wg, const float* __restrict__ bg){
    const int t = blockIdx.x*8 + threadIdx.y;
    if (t >= NTOK) return;
    const int lane = threadIdx.x;
    const float* xr = d_x2 + (size_t)t*Cn;
    float a0=0.f,a1=0.f,a2=0.f;
    for (int c=lane;c<Cn;c+=32){
        float v = xr[c];
        a0 = fmaf(v, wg[c*3+0], a0);
        a1 = fmaf(v, wg[c*3+1], a1);
        a2 = fmaf(v, wg[c*3+2], a2);
    }
    #pragma unroll
    for (int o=16;o>0;o>>=1){
        a0 += __shfl_xor_sync(0xffffffffu,a0,o);
        a1 += __shfl_xor_sync(0xffffffffu,a1,o);
        a2 += __shfl_xor_sync(0xffffffffu,a2,o);
    }
    if (lane==0){
        a0+=bg[0]; a1+=bg[1]; a2+=bg[2];
        int am=0; float m=a0;
        if (a1>m){m=a1;am=1;}
        if (a2>m){m=a2;am=2;}
        float e0=expf(a0-m), e1=expf(a1-m), e2=expf(a2-m);
        float sum=e0+e1+e2;
        float pm = ((am==0)?e0:(am==1)?e1:e2)/sum;
        d_eid[t]=am; d_mg[t]=pm;
    }
}

// denom[s,e] = sum_b mg (deterministic order)
__global__ void k_denom(){
    const int i = blockIdx.x*256 + threadIdx.x;
    if (i >= Sn*En) return;
    const int s = i/En, e = i%En;
    float acc = 0.f;
    #pragma unroll
    for (int b=0;b<Bn;b++){
        int t = b*Sn+s;
        if (d_eid[t]==e) acc += d_mg[t];
    }
    d_denom[i] = acc;
}

// gate score + expert bucket lists
__global__ void k_gs(){
    const int t = blockIdx.x*256 + threadIdx.x;
    if (t >= NTOK) return;
    const int e = d_eid[t], s = t % Sn;
    d_gs[t] = d_mg[t] / (d_denom[s*En+e] + 1e-6f) * (float)Bn;
    int pos = atomicAdd(&d_cnt[e], 1);
    d_list[e*NTOK + pos] = t;
}

// expert FFN layer 1 + exact GELU (gathered rows), fp16 out
__global__ void __launch_bounds__(256,2) k_moe1(const float* __restrict__ b1){
    const int e = blockIdx.z;
    const int cnt = d_cnt[e];
    const int* lst = d_list + e*NTOK;
    const __half* W = d_w1h + (size_t)e*Cn*HIDn;
    tgemm<false>(cnt,HIDn,Cn,
        [=] (int m,int k){ return d_x2h + (size_t)lst[m]*Cn + k; },
        [=] (int k,int n){ return W + (size_t)k*HIDn + n; },
        [=] (int m,int n,float v){
            float xg = v + b1[e*HIDn+n];
            float gl = 0.5f*xg*(1.f + erff(xg*0.70710678118654752f));
            d_hmid[(size_t)lst[m]*HIDn+n] = __float2half(gl);
        });
}

// expert FFN layer 2, scaled by gate score
__global__ void __launch_bounds__(256,2) k_moe2(const float* __restrict__ b2){
    const int e = blockIdx.z;
    const int cnt = d_cnt[e];
    const int* lst = d_list + e*NTOK;
    const __half* W = d_w2h + (size_t)e*HIDn*Cn;
    tgemm<false>(cnt,Cn,HIDn,
        [=] (int m,int k){ return d_hmid + (size_t)lst[m]*HIDn + k; },
        [=] (int k,int n){ return W + (size_t)k*Cn + n; },
        [=] (int m,int n,float v){
            int t = lst[m];
            d_moe[(size_t)t*Cn+n] = (v + b2[e*Cn+n]) * d_gs[t];
        });
}

// out[b,c,s] = x2[b,s,c] + moe[b,s,c]
__global__ void k_final(float* __restrict__ out){
    __shared__ float tile[32][33];
    const int b = blockIdx.z;
    const int s0 = blockIdx.x*32, c0 = blockIdx.y*32;
    {
        int s = s0+threadIdx.y, c = c0+threadIdx.x;
        if (s < Sn){
            size_t idx = ((size_t)b*Sn+s)*Cn + c;
            tile[threadIdx.y][threadIdx.x] = d_x2[idx] + d_moe[idx];
        }
    }
    __syncthreads();
    {
        int s = s0+threadIdx.x, c = c0+threadIdx.y;
        if (s < Sn)
            out[((size_t)b*Cn+c)*Sn + s] = tile[threadIdx.x][threadIdx.y];
    }
}

// ---------------- launch ------------------------------------------------------
extern "C" void kernel_launch(void* const* d_in, const int* in_sizes, int n_in,
                              void* d_out, int out_size){
    const float* x     = (const float*)d_in[0];
    const float* gam   = (const float*)d_in[1];
    const float* bet   = (const float*)d_in[2];
    const float* wqkv  = (const float*)d_in[3];
    const float* wout  = (const float*)d_in[4];
    const float* wgate = (const float*)d_in[5];
    const float* bgate = (const float*)d_in[6];
    const float* w1    = (const float*)d_in[7];
    const float* b1    = (const float*)d_in[8];
    const float* w2    = (const float*)d_in[9];
    const float* b2    = (const float*)d_in[10];
    float* out = (float*)d_out;

    cudaFuncSetAttribute(k_qkv,   cudaFuncAttributeMaxDynamicSharedMemorySize, GEMM_SMEM);
    cudaFuncSetAttribute(k_oproj, cudaFuncAttributeMaxDynamicSharedMemorySize, GEMM_SMEM);
    cudaFuncSetAttribute(k_moe1,  cudaFuncAttributeMaxDynamicSharedMemorySize, GEMM_SMEM);
    cudaFuncSetAttribute(k_moe2,  cudaFuncAttributeMaxDynamicSharedMemorySize, GEMM_SMEM);
    cudaFuncSetAttribute(k_attn,  cudaFuncAttributeMaxDynamicSharedMemorySize, ATT_SMEM);

    // weight fp16 conversion
    __half* wqkvh_p; cudaGetSymbolAddress((void**)&wqkvh_p, d_wqkvh);
    __half* wouth_p; cudaGetSymbolAddress((void**)&wouth_p, d_wouth);
    __half* w1h_p;   cudaGetSymbolAddress((void**)&w1h_p,   d_w1h);
    __half* w2h_p;   cudaGetSymbolAddress((void**)&w2h_p,   d_w2h);
    k_cvt<<<512,256>>>((const float4*)wqkv, (__half2*)wqkvh_p, Cn*3*Cn/4);
    k_cvt<<<512,256>>>((const float4*)wout, (__half2*)wouth_p, Cn*Cn/4);
    k_cvt<<<1024,256>>>((const float4*)w1,  (__half2*)w1h_p,   En*Cn*HIDn/4);
    k_cvt<<<1024,256>>>((const float4*)w2,  (__half2*)w2h_p,   En*HIDn*Cn/4);

    k_zero<<<1,32>>>();
    k_ln1<<<dim3(Bn,64), 256>>>(x);
    k_ln2<<<Bn, 64>>>();
    k_ln<<<dim3(23,24,Bn), dim3(32,32)>>>(x, gam, bet);
    k_qkv<<<dim3((NTOK+127)/128, (3*Cn)/128), 256, GEMM_SMEM>>>();
    k_attn<<<dim3(6, Bn*Hn), 256, ATT_SMEM>>>();
    k_oproj<<<dim3((NTOK+127)/128, Cn/128), 256, GEMM_SMEM>>>(x);
    k_gate<<<NTOK/8, dim3(32,8)>>>(wgate, bgate);
    k_denom<<<(Sn*En+255)/256, 256>>>();
    k_gs<<<(NTOK+255)/256, 256>>>();
    k_moe1<<<dim3((NTOK+127)/128, HIDn/128, En), 256, GEMM_SMEM>>>(b1);
    k_moe2<<<dim3((NTOK+127)/128, Cn/128, En), 256, GEMM_SMEM>>>(b2);
    k_final<<<dim3(23,24,Bn), dim3(32,32)>>>(out);
}